// round 4
// baseline (speedup 1.0000x reference)
#include <cuda_runtime.h>
#include <math.h>

// ---------------------------------------------------------------------------
// GAT, N=4096, NFEAT=2048, D=256, NCLASS=512, heads 4/4/6, alpha=0.2
// Sparse attention (adjacency ~1% dense -> neighbor lists), dense fp32 GEMMs
// for the projections only.
// ---------------------------------------------------------------------------

#define NNODE 4096
#define MAXN  1024   // per-row neighbor capacity (expected deg ~41)

// Scratch (device globals; no allocation allowed in kernel_launch)
__device__ float g_Wh[6L * 4096 * 512];     // per-head projections (max H=6, D=512)
__device__ float g_h1[4096L * 1024];        // layer-1 output (concat, double-elu)
__device__ float g_h2[4096L * 1024];        // layer-2 output
__device__ float g_f1[6 * 4096];
__device__ float g_f2[6 * 4096];
__device__ float g_cm[6 * 512];             // per-head column mean of Wh (deg==0 fallback)
__device__ int   g_nbr[4096L * MAXN];
__device__ int   g_deg[4096];

__device__ __forceinline__ float eluf(float x) { return x > 0.f ? x : expm1f(x); }

// --------------------------- neighbor-list build ---------------------------
// warp per row; ballot compaction gives deterministic in-order neighbor list.
__global__ __launch_bounds__(256) void build_nbr_k(const float* __restrict__ adj) {
    int warp = (blockIdx.x * blockDim.x + threadIdx.x) >> 5;
    int lane = threadIdx.x & 31;
    if (warp >= NNODE) return;
    const float* row = adj + (long)warp * NNODE;
    int* dst = g_nbr + (long)warp * MAXN;
    int base = 0;
    for (int j0 = 0; j0 < NNODE; j0 += 32) {
        float v = row[j0 + lane];
        unsigned m = __ballot_sync(0xffffffffu, v > 0.f);
        if (v > 0.f) {
            int pos = base + __popc(m & ((1u << lane) - 1u));
            if (pos < MAXN) dst[pos] = j0 + lane;
        }
        base += __popc(m);
    }
    if (lane == 0) g_deg[warp] = min(base, MAXN);
}

// --------------------------------- GEMM ------------------------------------
// C[z] = A @ B[z];  A:[M,K] row-major (shared over batch), B:[K,N], C:[M,N].
// 128x128x16 tile, 256 threads, 8x8 micro-tile (split-column B fragments).
#define BM 128
#define BN 128
#define BK 16

__global__ __launch_bounds__(256) void gemm_k(
    const float* __restrict__ A, const float* __restrict__ B,
    float* __restrict__ C, int M, int N, int K, long sB, long sC)
{
    __shared__ float As[BK][BM + 4];   // transposed A tile (pad vs bank conflicts)
    __shared__ float Bs[BK][BN];
    B += (long)blockIdx.z * sB;
    C += (long)blockIdx.z * sC;
    const int bm = blockIdx.y * BM, bn = blockIdx.x * BN;
    const int tid = threadIdx.x;
    const int tx = tid & 15, ty = tid >> 4;           // 16x16 thread grid
    const int arow = tid >> 2, acol = (tid & 3) * 4;  // A: 128 rows x 16 cols
    const int brow = tid >> 5, bcol = (tid & 31) * 4; // B: 16 rows x 128 cols

    float acc[8][8];
#pragma unroll
    for (int i = 0; i < 8; i++)
#pragma unroll
        for (int j = 0; j < 8; j++) acc[i][j] = 0.f;

    for (int k0 = 0; k0 < K; k0 += BK) {
#pragma unroll
        for (int i = 0; i < 2; i++) {
            int r = arow + i * 64;
            float4 v = *(const float4*)(A + (long)(bm + r) * K + (k0 + acol));
            As[acol + 0][r] = v.x; As[acol + 1][r] = v.y;
            As[acol + 2][r] = v.z; As[acol + 3][r] = v.w;
        }
#pragma unroll
        for (int i = 0; i < 2; i++) {
            int r = brow + i * 8;
            *(float4*)&Bs[r][bcol] =
                *(const float4*)(B + (long)(k0 + r) * N + (bn + bcol));
        }
        __syncthreads();
#pragma unroll
        for (int kk = 0; kk < BK; kk++) {
            float4 a0 = *(float4*)&As[kk][ty * 8];
            float4 a1 = *(float4*)&As[kk][ty * 8 + 4];
            // split-column B fragments: cols tx*4..+3 and 64+tx*4..+3
            float4 b0 = *(float4*)&Bs[kk][tx * 4];
            float4 b1 = *(float4*)&Bs[kk][64 + tx * 4];
            float av[8] = {a0.x, a0.y, a0.z, a0.w, a1.x, a1.y, a1.z, a1.w};
            float bv[8] = {b0.x, b0.y, b0.z, b0.w, b1.x, b1.y, b1.z, b1.w};
#pragma unroll
            for (int i = 0; i < 8; i++)
#pragma unroll
                for (int j = 0; j < 8; j++)
                    acc[i][j] = fmaf(av[i], bv[j], acc[i][j]);
        }
        __syncthreads();
    }
#pragma unroll
    for (int i = 0; i < 8; i++) {
        long base = (long)(bm + ty * 8 + i) * N + bn;
        *(float4*)(C + base + tx * 4) =
            make_float4(acc[i][0], acc[i][1], acc[i][2], acc[i][3]);
        *(float4*)(C + base + 64 + tx * 4) =
            make_float4(acc[i][4], acc[i][5], acc[i][6], acc[i][7]);
    }
}

// --------------------------- f1/f2 projections ----------------------------
// f1[h,n] = Wh[h,n,:] . a[h,0:D];  f2[h,n] = Wh[h,n,:] . a[h,D:2D]
__global__ __launch_bounds__(256) void f12_k(
    const float* __restrict__ Wh, const float* __restrict__ a, int D)
{
    int lane = threadIdx.x & 31;
    int n = (blockIdx.x * blockDim.x + threadIdx.x) >> 5;
    int h = blockIdx.y;
    if (n >= NNODE) return;
    const float* w  = Wh + ((long)h * NNODE + n) * D;
    const float* ah = a + h * 2 * D;
    float s1 = 0.f, s2 = 0.f;
    for (int d = lane; d < D; d += 32) {
        float v = w[d];
        s1 = fmaf(v, ah[d], s1);
        s2 = fmaf(v, ah[D + d], s2);
    }
    for (int off = 16; off; off >>= 1) {
        s1 += __shfl_down_sync(0xffffffffu, s1, off);
        s2 += __shfl_down_sync(0xffffffffu, s2, off);
    }
    if (lane == 0) { g_f1[h * NNODE + n] = s1; g_f2[h * NNODE + n] = s2; }
}

// column mean of Wh per head (fallback for isolated nodes: uniform softmax)
__global__ __launch_bounds__(256) void colmean_k(const float* __restrict__ Wh, int D)
{
    int d = blockIdx.x * blockDim.x + threadIdx.x;
    int h = blockIdx.y;
    if (d >= D) return;
    const float* base = Wh + (long)h * NNODE * D + d;
    float s = 0.f;
    for (int n = 0; n < NNODE; n++) s += base[(long)n * D];
    g_cm[h * D + d] = s * (1.f / NNODE);
}

// ------------------- sparse softmax + aggregate (concat) -------------------
// block = (node i, head h), 256 threads, D=256 (one output feature / thread).
// out[i, h*D + d] = elu(elu( sum_j softmax_j(lrelu(f1_i+f2_j)) * Wh[h,j,d] ))
__global__ __launch_bounds__(256) void agg_concat_k(
    const float* __restrict__ Wh, float* __restrict__ out, int H)
{
    const int D = 256;
    int i = blockIdx.x, h = blockIdx.y, t = threadIdx.x;
    __shared__ float sw[MAXN];
    __shared__ int   snb[MAXN];
    __shared__ float red[256];
    int dg = g_deg[i];
    const int* nb = g_nbr + (long)i * MAXN;
    float f1i = g_f1[h * NNODE + i];
    float lmax = -3.4e38f;
    for (int jj = t; jj < dg; jj += 256) {
        int j = nb[jj];
        snb[jj] = j;
        float e = f1i + g_f2[h * NNODE + j];
        e = e >= 0.f ? e : 0.2f * e;          // leaky_relu(alpha=0.2)
        sw[jj] = e;
        lmax = fmaxf(lmax, e);
    }
    red[t] = lmax; __syncthreads();
    for (int s = 128; s > 0; s >>= 1) { if (t < s) red[t] = fmaxf(red[t], red[t + s]); __syncthreads(); }
    float m = red[0]; __syncthreads();
    float lsum = 0.f;
    for (int jj = t; jj < dg; jj += 256) { float w = expf(sw[jj] - m); sw[jj] = w; lsum += w; }
    red[t] = lsum; __syncthreads();
    for (int s = 128; s > 0; s >>= 1) { if (t < s) red[t] += red[t + s]; __syncthreads(); }
    float inv = 1.f / red[0]; __syncthreads();

    float acc;
    if (dg > 0) {
        const float* whh = Wh + (long)h * NNODE * D;
        float a0 = 0.f, a1 = 0.f, a2 = 0.f, a3 = 0.f;
        int jj = 0;
        for (; jj + 4 <= dg; jj += 4) {
            const float* r0 = whh + (long)snb[jj + 0] * D;
            const float* r1 = whh + (long)snb[jj + 1] * D;
            const float* r2 = whh + (long)snb[jj + 2] * D;
            const float* r3 = whh + (long)snb[jj + 3] * D;
            a0 = fmaf(sw[jj + 0], r0[t], a0);
            a1 = fmaf(sw[jj + 1], r1[t], a1);
            a2 = fmaf(sw[jj + 2], r2[t], a2);
            a3 = fmaf(sw[jj + 3], r3[t], a3);
        }
        for (; jj < dg; jj++) a0 = fmaf(sw[jj], (whh + (long)snb[jj] * D)[t], a0);
        acc = ((a0 + a1) + (a2 + a3)) * inv;
    } else {
        acc = g_cm[h * D + t];                // uniform softmax over all nodes
    }
    acc = eluf(eluf(acc));                    // reference applies elu twice
    out[(long)i * (H * D) + h * D + t] = acc;
}

// ------------- output layer: 6 heads, mean, elu, L2-normalize -------------
// block = node i, 256 threads, D=512 (2 features / thread), loops 6 heads.
__global__ __launch_bounds__(256) void agg_mean_norm_k(
    const float* __restrict__ Wh, float* __restrict__ out)
{
    const int D = 512;
    int i = blockIdx.x, t = threadIdx.x;
    __shared__ float sw[MAXN];
    __shared__ int   snb[MAXN];
    __shared__ float red[256];
    int dg = g_deg[i];
    const int* nb = g_nbr + (long)i * MAXN;
    for (int jj = t; jj < dg; jj += 256) snb[jj] = nb[jj];
    __syncthreads();

    float acc0 = 0.f, acc1 = 0.f;
    for (int h = 0; h < 6; h++) {
        float f1i = g_f1[h * NNODE + i];
        float lmax = -3.4e38f;
        for (int jj = t; jj < dg; jj += 256) {
            float e = f1i + g_f2[h * NNODE + snb[jj]];
            e = e >= 0.f ? e : 0.2f * e;
            sw[jj] = e;
            lmax = fmaxf(lmax, e);
        }
        red[t] = lmax; __syncthreads();
        for (int s = 128; s > 0; s >>= 1) { if (t < s) red[t] = fmaxf(red[t], red[t + s]); __syncthreads(); }
        float m = red[0]; __syncthreads();
        float lsum = 0.f;
        for (int jj = t; jj < dg; jj += 256) { float w = expf(sw[jj] - m); sw[jj] = w; lsum += w; }
        red[t] = lsum; __syncthreads();
        for (int s = 128; s > 0; s >>= 1) { if (t < s) red[t] += red[t + s]; __syncthreads(); }
        float inv = 1.f / red[0]; __syncthreads();

        if (dg > 0) {
            const float* whh = Wh + (long)h * NNODE * D;
            float a0 = 0.f, a1 = 0.f;
            for (int jj = 0; jj < dg; jj++) {
                const float* r = whh + (long)snb[jj] * D;
                float w = sw[jj];
                a0 = fmaf(w, r[t], a0);
                a1 = fmaf(w, r[t + 256], a1);
            }
            acc0 += a0 * inv;
            acc1 += a1 * inv;
        } else {
            acc0 += g_cm[h * D + t];
            acc1 += g_cm[h * D + t + 256];
        }
        __syncthreads();   // sw reused next head
    }
    acc0 *= (1.f / 6.f); acc1 *= (1.f / 6.f);
    acc0 = eluf(acc0);   acc1 = eluf(acc1);
    red[t] = acc0 * acc0 + acc1 * acc1; __syncthreads();
    for (int s = 128; s > 0; s >>= 1) { if (t < s) red[t] += red[t + s]; __syncthreads(); }
    float nrm = sqrtf(red[0]);
    float inv2 = 1.f / fmaxf(nrm, 1e-12f);
    out[(long)i * D + t]       = acc0 * inv2;
    out[(long)i * D + t + 256] = acc1 * inv2;
}

// ------------------------------- launcher ----------------------------------
extern "C" void kernel_launch(void* const* d_in, const int* in_sizes, int n_in,
                              void* d_out, int out_size) {
    const float* x   = (const float*)d_in[0];   // [4096, 2048]
    const float* adj = (const float*)d_in[1];   // [4096, 4096]
    const float* W1  = (const float*)d_in[2];   // [4, 2048, 256]
    const float* a1  = (const float*)d_in[3];   // [4, 512]
    const float* W2  = (const float*)d_in[4];   // [4, 1024, 256]
    const float* a2  = (const float*)d_in[5];   // [4, 512]
    const float* W3  = (const float*)d_in[6];   // [6, 1024, 512]
    const float* a3  = (const float*)d_in[7];   // [6, 1024]
    float* out = (float*)d_out;                 // [4096, 512]

    float *pWh = nullptr, *ph1 = nullptr, *ph2 = nullptr;
    cudaGetSymbolAddress((void**)&pWh, g_Wh);
    cudaGetSymbolAddress((void**)&ph1, g_h1);
    cudaGetSymbolAddress((void**)&ph2, g_h2);

    // neighbor lists (4096 warps)
    build_nbr_k<<<512, 256>>>(adj);

    // ---- layer 1: H=4, K=2048, D=256 ----
    gemm_k<<<dim3(2, 32, 4), 256>>>(x, W1, pWh, NNODE, 256, 2048,
                                    2048L * 256, (long)NNODE * 256);
    f12_k<<<dim3(512, 4), 256>>>(pWh, a1, 256);
    colmean_k<<<dim3(1, 4), 256>>>(pWh, 256);
    agg_concat_k<<<dim3(NNODE, 4), 256>>>(pWh, ph1, 4);

    // ---- layer 2: H=4, K=1024, D=256 ----
    gemm_k<<<dim3(2, 32, 4), 256>>>(ph1, W2, pWh, NNODE, 256, 1024,
                                    1024L * 256, (long)NNODE * 256);
    f12_k<<<dim3(512, 4), 256>>>(pWh, a2, 256);
    colmean_k<<<dim3(1, 4), 256>>>(pWh, 256);
    agg_concat_k<<<dim3(NNODE, 4), 256>>>(pWh, ph2, 4);

    // ---- output layer: H=6, K=1024, D=512, mean+elu+normalize ----
    gemm_k<<<dim3(4, 32, 6), 256>>>(ph2, W3, pWh, NNODE, 512, 1024,
                                    1024L * 512, (long)NNODE * 512);
    f12_k<<<dim3(512, 6), 256>>>(pWh, a3, 512);
    colmean_k<<<dim3(2, 6), 256>>>(pWh, 512);
    agg_mean_norm_k<<<NNODE, 256>>>(pWh, out);
}

// round 5
// speedup vs baseline: 1.1744x; 1.1744x over previous
#include <cuda_runtime.h>
#include <math.h>

// ---------------------------------------------------------------------------
// GAT, N=4096, NFEAT=2048, D=256, NCLASS=512, heads 4/4/6, alpha=0.2
// Sparse attention (adjacency ~1% -> neighbor lists); dense fp32 GEMMs for the
// projections using packed fma.rn.f32x2 (Blackwell FFMA2) + double buffering.
// ---------------------------------------------------------------------------

#define NNODE 4096
#define MAXN  1024   // per-row neighbor capacity (expected deg ~41)

// Scratch (device globals; no allocation allowed in kernel_launch)
__device__ float g_Wh[6L * 4096 * 512];     // per-head projections (max H=6, D=512)
__device__ float g_h1[4096L * 1024];        // layer-1 output (concat, double-elu)
__device__ float g_h2[4096L * 1024];        // layer-2 output
__device__ float g_f1[6 * 4096];
__device__ float g_f2[6 * 4096];
__device__ float g_cm[6 * 512];             // per-head column mean of Wh (deg==0 fallback)
#define CMCH 32
__device__ float g_cmp[6L * CMCH * 512];    // colmean partials
__device__ int   g_nbr[4096L * MAXN];
__device__ int   g_deg[4096];

__device__ __forceinline__ float eluf(float x) { return x > 0.f ? x : expm1f(x); }

// packed fp32x2 helpers (sm_100+)
__device__ __forceinline__ unsigned long long pack2(float x, float y) {
    unsigned long long r;
    asm("mov.b64 %0, {%1, %2};" : "=l"(r) : "f"(x), "f"(y));
    return r;
}
__device__ __forceinline__ void ffma2(unsigned long long& d,
                                      unsigned long long a, unsigned long long b) {
    asm("fma.rn.f32x2 %0, %1, %2, %0;" : "+l"(d) : "l"(a), "l"(b));
}
__device__ __forceinline__ float2 unpack2(unsigned long long v) {
    float2 f;
    asm("mov.b64 {%0, %1}, %2;" : "=f"(f.x), "=f"(f.y) : "l"(v));
    return f;
}

// --------------------------- neighbor-list build ---------------------------
__global__ __launch_bounds__(256) void build_nbr_k(const float* __restrict__ adj) {
    int warp = (blockIdx.x * blockDim.x + threadIdx.x) >> 5;
    int lane = threadIdx.x & 31;
    if (warp >= NNODE) return;
    const float* row = adj + (long)warp * NNODE;
    int* dst = g_nbr + (long)warp * MAXN;
    int base = 0;
    for (int j0 = 0; j0 < NNODE; j0 += 32) {
        float v = row[j0 + lane];
        unsigned m = __ballot_sync(0xffffffffu, v > 0.f);
        if (v > 0.f) {
            int pos = base + __popc(m & ((1u << lane) - 1u));
            if (pos < MAXN) dst[pos] = j0 + lane;
        }
        base += __popc(m);
    }
    if (lane == 0) g_deg[warp] = min(base, MAXN);
}

// --------------------------------- GEMM ------------------------------------
// C[z] = A @ B[z];  A:[M,K] row-major (shared over batch), B:[K,N], C:[M,N].
// 128x128x16 tile, 256 threads, 8x8 micro-tile, FFMA2 packed math,
// double-buffered shared tiles.
#define BM 128
#define BN 128
#define BK 16

__global__ __launch_bounds__(256) void gemm_k(
    const float* __restrict__ A, const float* __restrict__ B,
    float* __restrict__ C, int M, int N, int K, long sB, long sC)
{
    __shared__ float As[2][BK][BM + 4];   // transposed A tile
    __shared__ float Bs[2][BK][BN];
    B += (long)blockIdx.z * sB;
    C += (long)blockIdx.z * sC;
    const int bm = blockIdx.y * BM, bn = blockIdx.x * BN;
    const int tid = threadIdx.x;
    const int tx = tid & 15, ty = tid >> 4;           // 16x16 thread grid
    const int arow = tid >> 2, acol = (tid & 3) * 4;  // A: 128 rows x 16 cols
    const int brow = tid >> 5, bcol = (tid & 31) * 4; // B: 16 rows x 128 cols

    unsigned long long acc2[8][4];
#pragma unroll
    for (int i = 0; i < 8; i++)
#pragma unroll
        for (int p = 0; p < 4; p++) acc2[i][p] = 0ull;

    const float* Ap0 = A + (long)(bm + arow) * K + acol;
    const float* Ap1 = A + (long)(bm + arow + 64) * K + acol;
    const float* Bp0 = B + (long)brow * N + bn + bcol;
    const float* Bp1 = B + (long)(brow + 8) * N + bn + bcol;

    float4 ra0, ra1, rb0, rb1;
    // prologue: tile 0
    ra0 = *(const float4*)(Ap0);
    ra1 = *(const float4*)(Ap1);
    rb0 = *(const float4*)(Bp0);
    rb1 = *(const float4*)(Bp1);
    {
        As[0][acol + 0][arow] = ra0.x; As[0][acol + 1][arow] = ra0.y;
        As[0][acol + 2][arow] = ra0.z; As[0][acol + 3][arow] = ra0.w;
        As[0][acol + 0][arow + 64] = ra1.x; As[0][acol + 1][arow + 64] = ra1.y;
        As[0][acol + 2][arow + 64] = ra1.z; As[0][acol + 3][arow + 64] = ra1.w;
        *(float4*)&Bs[0][brow][bcol] = rb0;
        *(float4*)&Bs[0][brow + 8][bcol] = rb1;
    }
    __syncthreads();

    const int nk = K / BK;
    for (int t = 0; t < nk; t++) {
        const int cur = t & 1;
        const bool has_next = (t + 1 < nk);
        if (has_next) {
            long ko = (long)(t + 1) * BK;
            ra0 = *(const float4*)(Ap0 + ko);
            ra1 = *(const float4*)(Ap1 + ko);
            rb0 = *(const float4*)(Bp0 + ko * N);
            rb1 = *(const float4*)(Bp1 + ko * N);
        }
#pragma unroll
        for (int kk = 0; kk < BK; kk++) {
            const float* asr = &As[cur][kk][0];
            float4 a0 = *(const float4*)(asr + ty * 8);
            float4 a1 = *(const float4*)(asr + ty * 8 + 4);
            const unsigned long long* b0p =
                (const unsigned long long*)&Bs[cur][kk][tx * 4];
            const unsigned long long* b1p =
                (const unsigned long long*)&Bs[cur][kk][64 + tx * 4];
            unsigned long long bv0 = b0p[0], bv1 = b0p[1];
            unsigned long long bv2 = b1p[0], bv3 = b1p[1];
            float av[8] = {a0.x, a0.y, a0.z, a0.w, a1.x, a1.y, a1.z, a1.w};
#pragma unroll
            for (int i = 0; i < 8; i++) {
                unsigned long long ai = pack2(av[i], av[i]);
                ffma2(acc2[i][0], ai, bv0);
                ffma2(acc2[i][1], ai, bv1);
                ffma2(acc2[i][2], ai, bv2);
                ffma2(acc2[i][3], ai, bv3);
            }
        }
        if (has_next) {
            const int nxt = cur ^ 1;
            As[nxt][acol + 0][arow] = ra0.x; As[nxt][acol + 1][arow] = ra0.y;
            As[nxt][acol + 2][arow] = ra0.z; As[nxt][acol + 3][arow] = ra0.w;
            As[nxt][acol + 0][arow + 64] = ra1.x; As[nxt][acol + 1][arow + 64] = ra1.y;
            As[nxt][acol + 2][arow + 64] = ra1.z; As[nxt][acol + 3][arow + 64] = ra1.w;
            *(float4*)&Bs[nxt][brow][bcol] = rb0;
            *(float4*)&Bs[nxt][brow + 8][bcol] = rb1;
        }
        __syncthreads();
    }

#pragma unroll
    for (int i = 0; i < 8; i++) {
        long base = (long)(bm + ty * 8 + i) * N + bn;
        float2 c0 = unpack2(acc2[i][0]), c1 = unpack2(acc2[i][1]);
        float2 c2 = unpack2(acc2[i][2]), c3 = unpack2(acc2[i][3]);
        *(float4*)(C + base + tx * 4)      = make_float4(c0.x, c0.y, c1.x, c1.y);
        *(float4*)(C + base + 64 + tx * 4) = make_float4(c2.x, c2.y, c3.x, c3.y);
    }
}

// --------------------------- f1/f2 projections ----------------------------
__global__ __launch_bounds__(256) void f12_k(
    const float* __restrict__ Wh, const float* __restrict__ a, int D)
{
    int lane = threadIdx.x & 31;
    int n = (blockIdx.x * blockDim.x + threadIdx.x) >> 5;
    int h = blockIdx.y;
    if (n >= NNODE) return;
    const float* w  = Wh + ((long)h * NNODE + n) * D;
    const float* ah = a + h * 2 * D;
    float s1 = 0.f, s2 = 0.f;
    for (int d = lane; d < D; d += 32) {
        float v = w[d];
        s1 = fmaf(v, ah[d], s1);
        s2 = fmaf(v, ah[D + d], s2);
    }
    for (int off = 16; off; off >>= 1) {
        s1 += __shfl_down_sync(0xffffffffu, s1, off);
        s2 += __shfl_down_sync(0xffffffffu, s2, off);
    }
    if (lane == 0) { g_f1[h * NNODE + n] = s1; g_f2[h * NNODE + n] = s2; }
}

// column mean of Wh per head (deg==0 fallback) — two-stage parallel reduction
__global__ __launch_bounds__(256) void colmean1_k(const float* __restrict__ Wh, int D)
{
    int chunk = blockIdx.x, h = blockIdx.y;
    const int per = NNODE / CMCH;  // 128 nodes per chunk
    const float* base = Wh + (long)h * NNODE * D + (long)chunk * per * D;
    for (int d = threadIdx.x; d < D; d += 256) {
        float s = 0.f;
        for (int n = 0; n < per; n++) s += base[(long)n * D + d];
        g_cmp[((long)h * CMCH + chunk) * D + d] = s;
    }
}
__global__ __launch_bounds__(256) void colmean2_k(int D)
{
    int d = blockIdx.x * blockDim.x + threadIdx.x;
    int h = blockIdx.y;
    if (d >= D) return;
    float s = 0.f;
    const float* p = g_cmp + (long)h * CMCH * D + d;
    for (int c = 0; c < CMCH; c++) s += p[(long)c * D];
    g_cm[h * D + d] = s * (1.f / NNODE);
}

// ------------------- sparse softmax + aggregate (concat) -------------------
__global__ __launch_bounds__(256) void agg_concat_k(
    const float* __restrict__ Wh, float* __restrict__ out, int H)
{
    const int D = 256;
    int i = blockIdx.x, h = blockIdx.y, t = threadIdx.x;
    __shared__ float sw[MAXN];
    __shared__ int   snb[MAXN];
    __shared__ float red[256];
    int dg = g_deg[i];
    const int* nb = g_nbr + (long)i * MAXN;
    float f1i = g_f1[h * NNODE + i];
    float lmax = -3.4e38f;
    for (int jj = t; jj < dg; jj += 256) {
        int j = nb[jj];
        snb[jj] = j;
        float e = f1i + g_f2[h * NNODE + j];
        e = e >= 0.f ? e : 0.2f * e;          // leaky_relu(alpha=0.2)
        sw[jj] = e;
        lmax = fmaxf(lmax, e);
    }
    red[t] = lmax; __syncthreads();
    for (int s = 128; s > 0; s >>= 1) { if (t < s) red[t] = fmaxf(red[t], red[t + s]); __syncthreads(); }
    float m = red[0]; __syncthreads();
    float lsum = 0.f;
    for (int jj = t; jj < dg; jj += 256) { float w = expf(sw[jj] - m); sw[jj] = w; lsum += w; }
    red[t] = lsum; __syncthreads();
    for (int s = 128; s > 0; s >>= 1) { if (t < s) red[t] += red[t + s]; __syncthreads(); }
    float inv = 1.f / red[0]; __syncthreads();

    float acc;
    if (dg > 0) {
        const float* whh = Wh + (long)h * NNODE * D;
        float a0 = 0.f, a1 = 0.f, a2 = 0.f, a3 = 0.f;
        int jj = 0;
        for (; jj + 4 <= dg; jj += 4) {
            const float* r0 = whh + (long)snb[jj + 0] * D;
            const float* r1 = whh + (long)snb[jj + 1] * D;
            const float* r2 = whh + (long)snb[jj + 2] * D;
            const float* r3 = whh + (long)snb[jj + 3] * D;
            a0 = fmaf(sw[jj + 0], r0[t], a0);
            a1 = fmaf(sw[jj + 1], r1[t], a1);
            a2 = fmaf(sw[jj + 2], r2[t], a2);
            a3 = fmaf(sw[jj + 3], r3[t], a3);
        }
        for (; jj < dg; jj++) a0 = fmaf(sw[jj], (whh + (long)snb[jj] * D)[t], a0);
        acc = ((a0 + a1) + (a2 + a3)) * inv;
    } else {
        acc = g_cm[h * D + t];                // uniform softmax over all nodes
    }
    acc = eluf(eluf(acc));                    // reference applies elu twice
    out[(long)i * (H * D) + h * D + t] = acc;
}

// ------------- output layer: 6 heads, mean, elu, L2-normalize -------------
__global__ __launch_bounds__(256) void agg_mean_norm_k(
    const float* __restrict__ Wh, float* __restrict__ out)
{
    const int D = 512;
    int i = blockIdx.x, t = threadIdx.x;
    __shared__ float sw[MAXN];
    __shared__ int   snb[MAXN];
    __shared__ float red[256];
    int dg = g_deg[i];
    const int* nb = g_nbr + (long)i * MAXN;
    for (int jj = t; jj < dg; jj += 256) snb[jj] = nb[jj];
    __syncthreads();

    float acc0 = 0.f, acc1 = 0.f;
    for (int h = 0; h < 6; h++) {
        float f1i = g_f1[h * NNODE + i];
        float lmax = -3.4e38f;
        for (int jj = t; jj < dg; jj += 256) {
            float e = f1i + g_f2[h * NNODE + snb[jj]];
            e = e >= 0.f ? e : 0.2f * e;
            sw[jj] = e;
            lmax = fmaxf(lmax, e);
        }
        red[t] = lmax; __syncthreads();
        for (int s = 128; s > 0; s >>= 1) { if (t < s) red[t] = fmaxf(red[t], red[t + s]); __syncthreads(); }
        float m = red[0]; __syncthreads();
        float lsum = 0.f;
        for (int jj = t; jj < dg; jj += 256) { float w = expf(sw[jj] - m); sw[jj] = w; lsum += w; }
        red[t] = lsum; __syncthreads();
        for (int s = 128; s > 0; s >>= 1) { if (t < s) red[t] += red[t + s]; __syncthreads(); }
        float inv = 1.f / red[0]; __syncthreads();

        if (dg > 0) {
            const float* whh = Wh + (long)h * NNODE * D;
            float a0 = 0.f, a1 = 0.f;
            for (int jj = 0; jj < dg; jj++) {
                const float* r = whh + (long)snb[jj] * D;
                float w = sw[jj];
                a0 = fmaf(w, r[t], a0);
                a1 = fmaf(w, r[t + 256], a1);
            }
            acc0 += a0 * inv;
            acc1 += a1 * inv;
        } else {
            acc0 += g_cm[h * D + t];
            acc1 += g_cm[h * D + t + 256];
        }
        __syncthreads();   // sw reused next head
    }
    acc0 *= (1.f / 6.f); acc1 *= (1.f / 6.f);
    acc0 = eluf(acc0);   acc1 = eluf(acc1);
    red[t] = acc0 * acc0 + acc1 * acc1; __syncthreads();
    for (int s = 128; s > 0; s >>= 1) { if (t < s) red[t] += red[t + s]; __syncthreads(); }
    float nrm = sqrtf(red[0]);
    float inv2 = 1.f / fmaxf(nrm, 1e-12f);
    out[(long)i * D + t]       = acc0 * inv2;
    out[(long)i * D + t + 256] = acc1 * inv2;
}

// ------------------------------- launcher ----------------------------------
extern "C" void kernel_launch(void* const* d_in, const int* in_sizes, int n_in,
                              void* d_out, int out_size) {
    const float* x   = (const float*)d_in[0];   // [4096, 2048]
    const float* adj = (const float*)d_in[1];   // [4096, 4096]
    const float* W1  = (const float*)d_in[2];   // [4, 2048, 256]
    const float* a1  = (const float*)d_in[3];   // [4, 512]
    const float* W2  = (const float*)d_in[4];   // [4, 1024, 256]
    const float* a2  = (const float*)d_in[5];   // [4, 512]
    const float* W3  = (const float*)d_in[6];   // [6, 1024, 512]
    const float* a3  = (const float*)d_in[7];   // [6, 1024]
    float* out = (float*)d_out;                 // [4096, 512]

    float *pWh = nullptr, *ph1 = nullptr, *ph2 = nullptr;
    cudaGetSymbolAddress((void**)&pWh, g_Wh);
    cudaGetSymbolAddress((void**)&ph1, g_h1);
    cudaGetSymbolAddress((void**)&ph2, g_h2);

    // neighbor lists (4096 warps)
    build_nbr_k<<<512, 256>>>(adj);

    // ---- layer 1: H=4, K=2048, D=256 ----
    gemm_k<<<dim3(2, 32, 4), 256>>>(x, W1, pWh, NNODE, 256, 2048,
                                    2048L * 256, (long)NNODE * 256);
    f12_k<<<dim3(512, 4), 256>>>(pWh, a1, 256);
    colmean1_k<<<dim3(CMCH, 4), 256>>>(pWh, 256);
    colmean2_k<<<dim3(1, 4), 256>>>(256);
    agg_concat_k<<<dim3(NNODE, 4), 256>>>(pWh, ph1, 4);

    // ---- layer 2: H=4, K=1024, D=256 ----
    gemm_k<<<dim3(2, 32, 4), 256>>>(ph1, W2, pWh, NNODE, 256, 1024,
                                    1024L * 256, (long)NNODE * 256);
    f12_k<<<dim3(512, 4), 256>>>(pWh, a2, 256);
    colmean1_k<<<dim3(CMCH, 4), 256>>>(pWh, 256);
    colmean2_k<<<dim3(1, 4), 256>>>(256);
    agg_concat_k<<<dim3(NNODE, 4), 256>>>(pWh, ph2, 4);

    // ---- output layer: H=6, K=1024, D=512, mean+elu+normalize ----
    gemm_k<<<dim3(4, 32, 6), 256>>>(ph2, W3, pWh, NNODE, 512, 1024,
                                    1024L * 512, (long)NNODE * 512);
    f12_k<<<dim3(512, 6), 256>>>(pWh, a3, 512);
    colmean1_k<<<dim3(CMCH, 6), 256>>>(pWh, 512);
    colmean2_k<<<dim3(2, 6), 256>>>(512);
    agg_mean_norm_k<<<NNODE, 256>>>(pWh, out);
}

// round 13
// speedup vs baseline: 1.8890x; 1.6084x over previous
#include <cuda_runtime.h>
#include <cuda_bf16.h>
#include <math.h>
#include <stdint.h>

// ---------------------------------------------------------------------------
// GAT, N=4096, NFEAT=2048, D=256, NCLASS=512, heads 4/4/6, alpha=0.2
// Sparse attention (adjacency ~1% -> neighbor lists).
// Projections via warp-level mma.sync bf16 (m16n8k16) with 3-term hi/lo split
// (fp32-accurate). tcgen05 is NOT available: harness PTX targets sm_103
// (no 'a' feature suffix), so only baseline-ISA tensor ops compile.
// ---------------------------------------------------------------------------

#define NNODE 4096
#define MAXN  1024

// Scratch (device globals)
__device__ float g_Wh[6L * 4096 * 512];                       // projections fp32
__device__ __align__(16) __nv_bfloat16 g_Ah[4096L * 2048];    // A operand hi
__device__ __align__(16) __nv_bfloat16 g_Al[4096L * 2048];    // A operand lo
__device__ __align__(16) __nv_bfloat16 g_Bh[6L * 512 * 1024]; // W^T hi [H][N][K]
__device__ __align__(16) __nv_bfloat16 g_Bl[6L * 512 * 1024]; // W^T lo
__device__ float g_f1[6 * 4096];
__device__ float g_f2[6 * 4096];
__device__ float g_cm[6 * 512];
#define CMCH 32
__device__ float g_cmp[6L * CMCH * 512];
__device__ int   g_nbr[4096L * MAXN];
__device__ int   g_deg[4096];

__device__ __forceinline__ float eluf(float x) { return x > 0.f ? x : expm1f(x); }

__device__ __forceinline__ uint32_t smem_to_u32(const void* p) {
    uint32_t a;
    asm("{ .reg .u64 t; cvta.to.shared.u64 t, %1; cvt.u32.u64 %0, t; }"
        : "=r"(a) : "l"(p));
    return a;
}
#define CPASYNC16(dst, src) \
    asm volatile("cp.async.cg.shared.global [%0], [%1], 16;" \
        :: "r"((uint32_t)(dst)), "l"(src) : "memory")
#define LDSM4(R0, R1, R2, R3, ADDR) \
    asm volatile("ldmatrix.sync.aligned.m8n8.x4.shared.b16 {%0,%1,%2,%3}, [%4];" \
        : "=r"(R0), "=r"(R1), "=r"(R2), "=r"(R3) : "r"(ADDR))
#define MMA16816(C, A, B0, B1) \
    asm volatile("mma.sync.aligned.m16n8k16.row.col.f32.bf16.bf16.f32 " \
        "{%0,%1,%2,%3}, {%4,%5,%6,%7}, {%8,%9}, {%0,%1,%2,%3};" \
        : "+f"((C)[0]), "+f"((C)[1]), "+f"((C)[2]), "+f"((C)[3]) \
        : "r"((A)[0]), "r"((A)[1]), "r"((A)[2]), "r"((A)[3]), \
          "r"(B0), "r"(B1))

// --------------------------- neighbor-list build ---------------------------
__global__ __launch_bounds__(256) void build_nbr_k(const float* __restrict__ adj) {
    int warp = (blockIdx.x * blockDim.x + threadIdx.x) >> 5;
    int lane = threadIdx.x & 31;
    if (warp >= NNODE) return;
    const float* row = adj + (long)warp * NNODE;
    int* dst = g_nbr + (long)warp * MAXN;
    int base = 0;
    for (int j0 = 0; j0 < NNODE; j0 += 32) {
        float v = row[j0 + lane];
        unsigned m = __ballot_sync(0xffffffffu, v > 0.f);
        if (v > 0.f) {
            int pos = base + __popc(m & ((1u << lane) - 1u));
            if (pos < MAXN) dst[pos] = j0 + lane;
        }
        base += __popc(m);
    }
    if (lane == 0) g_deg[warp] = min(base, MAXN);
}

// ------------------------- fp32 -> bf16 hi/lo split ------------------------
__global__ __launch_bounds__(256) void split_x_k(const float* __restrict__ x, long n) {
    long i = (long)blockIdx.x * blockDim.x + threadIdx.x;
    long stride = (long)gridDim.x * blockDim.x;
    for (; i < n; i += stride) {
        float v = x[i];
        __nv_bfloat16 h = __float2bfloat16(v);
        g_Ah[i] = h;
        g_Al[i] = __float2bfloat16(v - __bfloat162float(h));
    }
}

// W [H][K][N] fp32 -> Bh/Bl [H][N][K] bf16 (32x32 smem-tile transpose)
__global__ __launch_bounds__(256) void wsplit_k(const float* __restrict__ W, int K, int N) {
    __shared__ float tile[32][33];
    int h = blockIdx.z;
    int k0 = blockIdx.x * 32, n0 = blockIdx.y * 32;
    int tx = threadIdx.x & 31, ty = threadIdx.x >> 5;   // 32 x 8
    const float* Wp = W + (long)h * K * N;
#pragma unroll
    for (int i = 0; i < 4; i++)
        tile[ty + i * 8][tx] = Wp[(long)(k0 + ty + i * 8) * N + n0 + tx];
    __syncthreads();
#pragma unroll
    for (int i = 0; i < 4; i++) {
        int n = n0 + ty + i * 8, k = k0 + tx;
        float v = tile[tx][ty + i * 8];
        __nv_bfloat16 hv = __float2bfloat16(v);
        long o = ((long)h * N + n) * K + k;
        g_Bh[o] = hv;
        g_Bl[o] = __float2bfloat16(v - __bfloat162float(hv));
    }
}

// -------------------- warp-MMA GEMM (3-term bf16 split) --------------------
// C[h] = A @ B[h]^T; A hi/lo: [4096,K] bf16; B hi/lo: [H][N][K] bf16 (K-major)
// C: [H][4096][N] fp32. CTA tile 128x128, 8 warps (2x4), warp tile 64x32.
// K-chunk 32; per k16: 48 HMMA/warp (AhBh + AhBl + AlBh into one fp32 acc).
#define KC 32
#define PB 40      // smem row pitch in bf16 (80 bytes, 16B-aligned, 5r%8 perm)

__global__ void __launch_bounds__(256, 2) mma_gemm_k(
    const __nv_bfloat16* __restrict__ Ah, const __nv_bfloat16* __restrict__ Al,
    const __nv_bfloat16* __restrict__ Bh, const __nv_bfloat16* __restrict__ Bl,
    float* __restrict__ C, int K, int N)
{
    __shared__ __align__(16) __nv_bfloat16 sAh[128 * PB], sAl[128 * PB];
    __shared__ __align__(16) __nv_bfloat16 sBh[128 * PB], sBl[128 * PB];

    const int tid = threadIdx.x, lane = tid & 31, wid = tid >> 5;
    const int m0 = blockIdx.y * 128, n0 = blockIdx.x * 128, h = blockIdx.z;
    const int wm = (wid & 1) * 64;        // warp m offset
    const int wn = (wid >> 1) * 32;       // warp n offset

    const uint32_t uAh = smem_to_u32(sAh), uAl = smem_to_u32(sAl);
    const uint32_t uBh = smem_to_u32(sBh), uBl = smem_to_u32(sBl);

    // ---- global->smem chunk mapping: 512 16B-chunks per tile, 2 per thread
    const int r0 = tid >> 2, s0 = (tid & 3);            // chunk tid
    const int r1 = (tid + 256) >> 2, s1 = ((tid + 256) & 3);
    const uint32_t d0 = (uint32_t)r0 * 80u + (uint32_t)s0 * 16u;
    const uint32_t d1 = (uint32_t)r1 * 80u + (uint32_t)s1 * 16u;
    const __nv_bfloat16* pA0h = Ah + (long)(m0 + r0) * K + s0 * 8;
    const __nv_bfloat16* pA1h = Ah + (long)(m0 + r1) * K + s1 * 8;
    const __nv_bfloat16* pA0l = Al + (long)(m0 + r0) * K + s0 * 8;
    const __nv_bfloat16* pA1l = Al + (long)(m0 + r1) * K + s1 * 8;
    const __nv_bfloat16* pB0h = Bh + ((long)h * N + n0 + r0) * K + s0 * 8;
    const __nv_bfloat16* pB1h = Bh + ((long)h * N + n0 + r1) * K + s1 * 8;
    const __nv_bfloat16* pB0l = Bl + ((long)h * N + n0 + r0) * K + s0 * 8;
    const __nv_bfloat16* pB1l = Bl + ((long)h * N + n0 + r1) * K + s1 * 8;

    // ---- ldmatrix lane address offsets (bytes, before kk/atom offsets)
    const uint32_t aoff = (uint32_t)(wm + (lane & 15)) * 80u + (uint32_t)(lane >> 4) * 16u;
    const uint32_t boff = (uint32_t)(wn + (lane & 7) + ((lane >> 4) << 3)) * 80u
                        + (uint32_t)((lane >> 3) & 1) * 16u;

    float acc[4][4][4];
#pragma unroll
    for (int i = 0; i < 4; i++)
#pragma unroll
        for (int j = 0; j < 4; j++)
#pragma unroll
            for (int q = 0; q < 4; q++) acc[i][j][q] = 0.f;

    const int nk = K / KC;
    for (int t = 0; t < nk; t++) {
        const long ko = (long)t * KC;
        CPASYNC16(uAh + d0, pA0h + ko);  CPASYNC16(uAh + d1, pA1h + ko);
        CPASYNC16(uAl + d0, pA0l + ko);  CPASYNC16(uAl + d1, pA1l + ko);
        CPASYNC16(uBh + d0, pB0h + ko);  CPASYNC16(uBh + d1, pB1h + ko);
        CPASYNC16(uBl + d0, pB0l + ko);  CPASYNC16(uBl + d1, pB1l + ko);
        asm volatile("cp.async.commit_group;" ::: "memory");
        asm volatile("cp.async.wait_group 0;" ::: "memory");
        __syncthreads();

#pragma unroll
        for (int kk = 0; kk < 2; kk++) {
            const uint32_t kb = kk * 32;    // 16 bf16 = 32 bytes
            uint32_t af[4][4], bh[2][4], bl[2][4];
#pragma unroll
            for (int ma = 0; ma < 4; ma++)
                LDSM4(af[ma][0], af[ma][1], af[ma][2], af[ma][3],
                      uAh + aoff + ma * 1280u + kb);
#pragma unroll
            for (int g = 0; g < 2; g++) {
                LDSM4(bh[g][0], bh[g][1], bh[g][2], bh[g][3],
                      uBh + boff + g * 1280u + kb);
                LDSM4(bl[g][0], bl[g][1], bl[g][2], bl[g][3],
                      uBl + boff + g * 1280u + kb);
            }
            // terms Ah*Bh and Ah*Bl
#pragma unroll
            for (int ma = 0; ma < 4; ma++)
#pragma unroll
                for (int na = 0; na < 4; na++) {
                    const int g = na >> 1, p = (na & 1) * 2;
                    MMA16816(acc[ma][na], af[ma], bh[g][p], bh[g][p + 1]);
                    MMA16816(acc[ma][na], af[ma], bl[g][p], bl[g][p + 1]);
                }
            // reload Al over af, term Al*Bh
#pragma unroll
            for (int ma = 0; ma < 4; ma++)
                LDSM4(af[ma][0], af[ma][1], af[ma][2], af[ma][3],
                      uAl + aoff + ma * 1280u + kb);
#pragma unroll
            for (int ma = 0; ma < 4; ma++)
#pragma unroll
                for (int na = 0; na < 4; na++) {
                    const int g = na >> 1, p = (na & 1) * 2;
                    MMA16816(acc[ma][na], af[ma], bh[g][p], bh[g][p + 1]);
                }
        }
        __syncthreads();
    }

    // ---- epilogue: acc layout m16n8 -> C
    float* Ch = C + (long)h * NNODE * N;
#pragma unroll
    for (int ma = 0; ma < 4; ma++) {
        const int row = m0 + wm + ma * 16 + (lane >> 2);
#pragma unroll
        for (int na = 0; na < 4; na++) {
            const int col = n0 + wn + na * 8 + (lane & 3) * 2;
            float* p = Ch + (long)row * N + col;
            *(float2*)p             = make_float2(acc[ma][na][0], acc[ma][na][1]);
            *(float2*)(p + 8L * N)  = make_float2(acc[ma][na][2], acc[ma][na][3]);
        }
    }
}

// --------------------------- f1/f2 projections ----------------------------
__global__ __launch_bounds__(256) void f12_k(
    const float* __restrict__ Wh, const float* __restrict__ a, int D)
{
    int lane = threadIdx.x & 31;
    int n = (blockIdx.x * blockDim.x + threadIdx.x) >> 5;
    int h = blockIdx.y;
    if (n >= NNODE) return;
    const float* w  = Wh + ((long)h * NNODE + n) * D;
    const float* ah = a + h * 2 * D;
    float s1 = 0.f, s2 = 0.f;
    for (int d = lane; d < D; d += 32) {
        float v = w[d];
        s1 = fmaf(v, ah[d], s1);
        s2 = fmaf(v, ah[D + d], s2);
    }
    for (int off = 16; off; off >>= 1) {
        s1 += __shfl_down_sync(0xffffffffu, s1, off);
        s2 += __shfl_down_sync(0xffffffffu, s2, off);
    }
    if (lane == 0) { g_f1[h * NNODE + n] = s1; g_f2[h * NNODE + n] = s2; }
}

// column mean of Wh per head (deg==0 fallback) — two-stage reduction
__global__ __launch_bounds__(256) void colmean1_k(const float* __restrict__ Wh, int D)
{
    int chunk = blockIdx.x, h = blockIdx.y;
    const int per = NNODE / CMCH;
    const float* base = Wh + (long)h * NNODE * D + (long)chunk * per * D;
    for (int d = threadIdx.x; d < D; d += 256) {
        float s = 0.f;
        for (int n = 0; n < per; n++) s += base[(long)n * D + d];
        g_cmp[((long)h * CMCH + chunk) * D + d] = s;
    }
}
__global__ __launch_bounds__(256) void colmean2_k(int D)
{
    int d = blockIdx.x * blockDim.x + threadIdx.x;
    int h = blockIdx.y;
    if (d >= D) return;
    float s = 0.f;
    const float* p = g_cmp + (long)h * CMCH * D + d;
    for (int c = 0; c < CMCH; c++) s += p[(long)c * D];
    g_cm[h * D + d] = s * (1.f / NNODE);
}

// ------------------- sparse softmax + aggregate (concat) -------------------
// Writes the next layer's A operand directly as bf16 hi/lo.
__global__ __launch_bounds__(256) void agg_concat_k(
    const float* __restrict__ Wh, int H)
{
    const int D = 256;
    int i = blockIdx.x, h = blockIdx.y, t = threadIdx.x;
    __shared__ float sw[MAXN];
    __shared__ int   snb[MAXN];
    __shared__ float red[256];
    int dg = g_deg[i];
    const int* nb = g_nbr + (long)i * MAXN;
    float f1i = g_f1[h * NNODE + i];
    float lmax = -3.4e38f;
    for (int jj = t; jj < dg; jj += 256) {
        int j = nb[jj];
        snb[jj] = j;
        float e = f1i + g_f2[h * NNODE + j];
        e = e >= 0.f ? e : 0.2f * e;          // leaky_relu(alpha=0.2)
        sw[jj] = e;
        lmax = fmaxf(lmax, e);
    }
    red[t] = lmax; __syncthreads();
    for (int s = 128; s > 0; s >>= 1) { if (t < s) red[t] = fmaxf(red[t], red[t + s]); __syncthreads(); }
    float m = red[0]; __syncthreads();
    float lsum = 0.f;
    for (int jj = t; jj < dg; jj += 256) { float w = expf(sw[jj] - m); sw[jj] = w; lsum += w; }
    red[t] = lsum; __syncthreads();
    for (int s = 128; s > 0; s >>= 1) { if (t < s) red[t] += red[t + s]; __syncthreads(); }
    float inv = 1.f / red[0]; __syncthreads();

    float acc;
    if (dg > 0) {
        const float* whh = Wh + (long)h * NNODE * D;
        float a0 = 0.f, a1 = 0.f, a2 = 0.f, a3 = 0.f;
        int jj = 0;
        for (; jj + 4 <= dg; jj += 4) {
            a0 = fmaf(sw[jj + 0], (whh + (long)snb[jj + 0] * D)[t], a0);
            a1 = fmaf(sw[jj + 1], (whh + (long)snb[jj + 1] * D)[t], a1);
            a2 = fmaf(sw[jj + 2], (whh + (long)snb[jj + 2] * D)[t], a2);
            a3 = fmaf(sw[jj + 3], (whh + (long)snb[jj + 3] * D)[t], a3);
        }
        for (; jj < dg; jj++) a0 = fmaf(sw[jj], (whh + (long)snb[jj] * D)[t], a0);
        acc = ((a0 + a1) + (a2 + a3)) * inv;
    } else {
        acc = g_cm[h * D + t];                // uniform softmax over all nodes
    }
    acc = eluf(eluf(acc));                    // reference applies elu twice
    __nv_bfloat16 hv = __float2bfloat16(acc);
    long o = (long)i * (H * D) + h * D + t;
    g_Ah[o] = hv;
    g_Al[o] = __float2bfloat16(acc - __bfloat162float(hv));
}

// ------------- output layer: 6 heads, mean, elu, L2-normalize -------------
__global__ __launch_bounds__(256) void agg_mean_norm_k(
    const float* __restrict__ Wh, float* __restrict__ out)
{
    const int D = 512;
    int i = blockIdx.x, t = threadIdx.x;
    __shared__ float sw[MAXN];
    __shared__ int   snb[MAXN];
    __shared__ float red[256];
    int dg = g_deg[i];
    const int* nb = g_nbr + (long)i * MAXN;
    for (int jj = t; jj < dg; jj += 256) snb[jj] = nb[jj];
    __syncthreads();

    float acc0 = 0.f, acc1 = 0.f;
    for (int h = 0; h < 6; h++) {
        float f1i = g_f1[h * NNODE + i];
        float lmax = -3.4e38f;
        for (int jj = t; jj < dg; jj += 256) {
            float e = f1i + g_f2[h * NNODE + snb[jj]];
            e = e >= 0.f ? e : 0.2f * e;
            sw[jj] = e;
            lmax = fmaxf(lmax, e);
        }
        red[t] = lmax; __syncthreads();
        for (int s = 128; s > 0; s >>= 1) { if (t < s) red[t] = fmaxf(red[t], red[t + s]); __syncthreads(); }
        float m = red[0]; __syncthreads();
        float lsum = 0.f;
        for (int jj = t; jj < dg; jj += 256) { float w = expf(sw[jj] - m); sw[jj] = w; lsum += w; }
        red[t] = lsum; __syncthreads();
        for (int s = 128; s > 0; s >>= 1) { if (t < s) red[t] += red[t + s]; __syncthreads(); }
        float inv = 1.f / red[0]; __syncthreads();

        if (dg > 0) {
            const float* whh = Wh + (long)h * NNODE * D;
            float a0 = 0.f, a1 = 0.f;
            for (int jj = 0; jj < dg; jj++) {
                const float* r = whh + (long)snb[jj] * D;
                float w = sw[jj];
                a0 = fmaf(w, r[t], a0);
                a1 = fmaf(w, r[t + 256], a1);
            }
            acc0 += a0 * inv;
            acc1 += a1 * inv;
        } else {
            acc0 += g_cm[h * D + t];
            acc1 += g_cm[h * D + t + 256];
        }
        __syncthreads();
    }
    acc0 *= (1.f / 6.f); acc1 *= (1.f / 6.f);
    acc0 = eluf(acc0);   acc1 = eluf(acc1);
    red[t] = acc0 * acc0 + acc1 * acc1; __syncthreads();
    for (int s = 128; s > 0; s >>= 1) { if (t < s) red[t] += red[t + s]; __syncthreads(); }
    float nrm = sqrtf(red[0]);
    float inv2 = 1.f / fmaxf(nrm, 1e-12f);
    out[(long)i * D + t]       = acc0 * inv2;
    out[(long)i * D + t + 256] = acc1 * inv2;
}

// ------------------------------- launcher ----------------------------------
extern "C" void kernel_launch(void* const* d_in, const int* in_sizes, int n_in,
                              void* d_out, int out_size) {
    const float* x   = (const float*)d_in[0];   // [4096, 2048]
    const float* adj = (const float*)d_in[1];   // [4096, 4096]
    const float* W1  = (const float*)d_in[2];   // [4, 2048, 256]
    const float* a1  = (const float*)d_in[3];   // [4, 512]
    const float* W2  = (const float*)d_in[4];   // [4, 1024, 256]
    const float* a2  = (const float*)d_in[5];   // [4, 512]
    const float* W3  = (const float*)d_in[6];   // [6, 1024, 512]
    const float* a3  = (const float*)d_in[7];   // [6, 1024]
    float* out = (float*)d_out;                 // [4096, 512]

    float* pWh = nullptr;
    __nv_bfloat16 *pAh = nullptr, *pAl = nullptr, *pBh = nullptr, *pBl = nullptr;
    cudaGetSymbolAddress((void**)&pWh, g_Wh);
    cudaGetSymbolAddress((void**)&pAh, g_Ah);
    cudaGetSymbolAddress((void**)&pAl, g_Al);
    cudaGetSymbolAddress((void**)&pBh, g_Bh);
    cudaGetSymbolAddress((void**)&pBl, g_Bl);

    build_nbr_k<<<512, 256>>>(adj);

    // ---- layer 1: H=4, K=2048, N(out)=256 ----
    split_x_k<<<4096, 256>>>(x, 4096L * 2048);
    wsplit_k<<<dim3(64, 8, 4), 256>>>(W1, 2048, 256);
    mma_gemm_k<<<dim3(2, 32, 4), 256>>>(pAh, pAl, pBh, pBl, pWh, 2048, 256);
    f12_k<<<dim3(512, 4), 256>>>(pWh, a1, 256);
    colmean1_k<<<dim3(CMCH, 4), 256>>>(pWh, 256);
    colmean2_k<<<dim3(1, 4), 256>>>(256);
    agg_concat_k<<<dim3(NNODE, 4), 256>>>(pWh, 4);   // writes g_Ah/g_Al [4096,1024]

    // ---- layer 2: H=4, K=1024, N(out)=256 ----
    wsplit_k<<<dim3(32, 8, 4), 256>>>(W2, 1024, 256);
    mma_gemm_k<<<dim3(2, 32, 4), 256>>>(pAh, pAl, pBh, pBl, pWh, 1024, 256);
    f12_k<<<dim3(512, 4), 256>>>(pWh, a2, 256);
    colmean1_k<<<dim3(CMCH, 4), 256>>>(pWh, 256);
    colmean2_k<<<dim3(1, 4), 256>>>(256);
    agg_concat_k<<<dim3(NNODE, 4), 256>>>(pWh, 4);   // writes g_Ah/g_Al [4096,1024]

    // ---- output layer: H=6, K=1024, N(out)=512, mean+elu+normalize ----
    wsplit_k<<<dim3(32, 16, 6), 256>>>(W3, 1024, 512);
    mma_gemm_k<<<dim3(4, 32, 6), 256>>>(pAh, pAl, pBh, pBl, pWh, 1024, 512);
    f12_k<<<dim3(512, 6), 256>>>(pWh, a3, 512);
    colmean1_k<<<dim3(CMCH, 6), 256>>>(pWh, 512);
    colmean2_k<<<dim3(2, 6), 256>>>(512);
    agg_mean_norm_k<<<NNODE, 256>>>(pWh, out);
}

// round 14
// speedup vs baseline: 1.8909x; 1.0010x over previous
#include <cuda_runtime.h>
#include <cuda_bf16.h>
#include <math.h>
#include <stdint.h>

// ---------------------------------------------------------------------------
// GAT, N=4096, NFEAT=2048, D=256, NCLASS=512, heads 4/4/6, alpha=0.2
// Sparse attention (adjacency ~1% -> neighbor lists).
// Projections via warp-level mma.sync bf16 (m16n8k16) with 3-term hi/lo split
// (fp32-accurate). tcgen05 is NOT available: harness PTX targets sm_103
// (no 'a' feature suffix), so only baseline-ISA tensor ops compile.
// ---------------------------------------------------------------------------

#define NNODE 4096
#define MAXN  1024

// Scratch (device globals)
__device__ float g_Wh[6L * 4096 * 512];                       // projections fp32
__device__ __align__(16) __nv_bfloat16 g_Ah[4096L * 2048];    // A operand hi
__device__ __align__(16) __nv_bfloat16 g_Al[4096L * 2048];    // A operand lo
__device__ __align__(16) __nv_bfloat16 g_Bh[6L * 512 * 1024]; // W^T hi [H][N][K]
__device__ __align__(16) __nv_bfloat16 g_Bl[6L * 512 * 1024]; // W^T lo
__device__ float g_f1[6 * 4096];
__device__ float g_f2[6 * 4096];
__device__ float g_cm[6 * 512];
#define CMCH 32
__device__ float g_cmp[6L * CMCH * 512];
__device__ int   g_nbr[4096L * MAXN];
__device__ int   g_deg[4096];

__device__ __forceinline__ float eluf(float x) { return x > 0.f ? x : expm1f(x); }

__device__ __forceinline__ uint32_t smem_to_u32(const void* p) {
    uint32_t a;
    asm("{ .reg .u64 t; cvta.to.shared.u64 t, %1; cvt.u32.u64 %0, t; }"
        : "=r"(a) : "l"(p));
    return a;
}
#define CPASYNC16(dst, src) \
    asm volatile("cp.async.cg.shared.global [%0], [%1], 16;" \
        :: "r"((uint32_t)(dst)), "l"(src) : "memory")
#define LDSM4(R0, R1, R2, R3, ADDR) \
    asm volatile("ldmatrix.sync.aligned.m8n8.x4.shared.b16 {%0,%1,%2,%3}, [%4];" \
        : "=r"(R0), "=r"(R1), "=r"(R2), "=r"(R3) : "r"(ADDR))
#define MMA16816(C, A, B0, B1) \
    asm volatile("mma.sync.aligned.m16n8k16.row.col.f32.bf16.bf16.f32 " \
        "{%0,%1,%2,%3}, {%4,%5,%6,%7}, {%8,%9}, {%0,%1,%2,%3};" \
        : "+f"((C)[0]), "+f"((C)[1]), "+f"((C)[2]), "+f"((C)[3]) \
        : "r"((A)[0]), "r"((A)[1]), "r"((A)[2]), "r"((A)[3]), \
          "r"(B0), "r"(B1))

// --------------------------- neighbor-list build ---------------------------
__global__ __launch_bounds__(256) void build_nbr_k(const float* __restrict__ adj) {
    int warp = (blockIdx.x * blockDim.x + threadIdx.x) >> 5;
    int lane = threadIdx.x & 31;
    if (warp >= NNODE) return;
    const float* row = adj + (long)warp * NNODE;
    int* dst = g_nbr + (long)warp * MAXN;
    int base = 0;
    for (int j0 = 0; j0 < NNODE; j0 += 32) {
        float v = row[j0 + lane];
        unsigned m = __ballot_sync(0xffffffffu, v > 0.f);
        if (v > 0.f) {
            int pos = base + __popc(m & ((1u << lane) - 1u));
            if (pos < MAXN) dst[pos] = j0 + lane;
        }
        base += __popc(m);
    }
    if (lane == 0) g_deg[warp] = min(base, MAXN);
}

// ------------------------- fp32 -> bf16 hi/lo split ------------------------
__global__ __launch_bounds__(256) void split_x_k(const float* __restrict__ x, long n) {
    long i = (long)blockIdx.x * blockDim.x + threadIdx.x;
    long stride = (long)gridDim.x * blockDim.x;
    for (; i < n; i += stride) {
        float v = x[i];
        __nv_bfloat16 h = __float2bfloat16(v);
        g_Ah[i] = h;
        g_Al[i] = __float2bfloat16(v - __bfloat162float(h));
    }
}

// W [H][K][N] fp32 -> Bh/Bl [H][N][K] bf16 (32x32 smem-tile transpose)
__global__ __launch_bounds__(256) void wsplit_k(const float* __restrict__ W, int K, int N) {
    __shared__ float tile[32][33];
    int h = blockIdx.z;
    int k0 = blockIdx.x * 32, n0 = blockIdx.y * 32;
    int tx = threadIdx.x & 31, ty = threadIdx.x >> 5;   // 32 x 8
    const float* Wp = W + (long)h * K * N;
#pragma unroll
    for (int i = 0; i < 4; i++)
        tile[ty + i * 8][tx] = Wp[(long)(k0 + ty + i * 8) * N + n0 + tx];
    __syncthreads();
#pragma unroll
    for (int i = 0; i < 4; i++) {
        int n = n0 + ty + i * 8, k = k0 + tx;
        float v = tile[tx][ty + i * 8];
        __nv_bfloat16 hv = __float2bfloat16(v);
        long o = ((long)h * N + n) * K + k;
        g_Bh[o] = hv;
        g_Bl[o] = __float2bfloat16(v - __bfloat162float(hv));
    }
}

// -------------------- warp-MMA GEMM (3-term bf16 split) --------------------
// C[h] = A @ B[h]^T; A hi/lo: [4096,K] bf16; B hi/lo: [H][N][K] bf16 (K-major)
// C: [H][4096][N] fp32. CTA tile 128x128, 8 warps (2x4), warp tile 64x32.
// K-chunk 32; per k16: 48 HMMA/warp (AhBh + AhBl + AlBh into one fp32 acc).
#define KC 32
#define PB 40      // smem row pitch in bf16 (80 bytes, 16B-aligned, 5r%8 perm)

__global__ void __launch_bounds__(256, 2) mma_gemm_k(
    const __nv_bfloat16* __restrict__ Ah, const __nv_bfloat16* __restrict__ Al,
    const __nv_bfloat16* __restrict__ Bh, const __nv_bfloat16* __restrict__ Bl,
    float* __restrict__ C, int K, int N)
{
    __shared__ __align__(16) __nv_bfloat16 sAh[128 * PB], sAl[128 * PB];
    __shared__ __align__(16) __nv_bfloat16 sBh[128 * PB], sBl[128 * PB];

    const int tid = threadIdx.x, lane = tid & 31, wid = tid >> 5;
    const int m0 = blockIdx.y * 128, n0 = blockIdx.x * 128, h = blockIdx.z;
    const int wm = (wid & 1) * 64;        // warp m offset
    const int wn = (wid >> 1) * 32;       // warp n offset

    const uint32_t uAh = smem_to_u32(sAh), uAl = smem_to_u32(sAl);
    const uint32_t uBh = smem_to_u32(sBh), uBl = smem_to_u32(sBl);

    // ---- global->smem chunk mapping: 512 16B-chunks per tile, 2 per thread
    const int r0 = tid >> 2, s0 = (tid & 3);            // chunk tid
    const int r1 = (tid + 256) >> 2, s1 = ((tid + 256) & 3);
    const uint32_t d0 = (uint32_t)r0 * 80u + (uint32_t)s0 * 16u;
    const uint32_t d1 = (uint32_t)r1 * 80u + (uint32_t)s1 * 16u;
    const __nv_bfloat16* pA0h = Ah + (long)(m0 + r0) * K + s0 * 8;
    const __nv_bfloat16* pA1h = Ah + (long)(m0 + r1) * K + s1 * 8;
    const __nv_bfloat16* pA0l = Al + (long)(m0 + r0) * K + s0 * 8;
    const __nv_bfloat16* pA1l = Al + (long)(m0 + r1) * K + s1 * 8;
    const __nv_bfloat16* pB0h = Bh + ((long)h * N + n0 + r0) * K + s0 * 8;
    const __nv_bfloat16* pB1h = Bh + ((long)h * N + n0 + r1) * K + s1 * 8;
    const __nv_bfloat16* pB0l = Bl + ((long)h * N + n0 + r0) * K + s0 * 8;
    const __nv_bfloat16* pB1l = Bl + ((long)h * N + n0 + r1) * K + s1 * 8;

    // ---- ldmatrix lane address offsets (bytes, before kk/atom offsets)
    const uint32_t aoff = (uint32_t)(wm + (lane & 15)) * 80u + (uint32_t)(lane >> 4) * 16u;
    const uint32_t boff = (uint32_t)(wn + (lane & 7) + ((lane >> 4) << 3)) * 80u
                        + (uint32_t)((lane >> 3) & 1) * 16u;

    float acc[4][4][4];
#pragma unroll
    for (int i = 0; i < 4; i++)
#pragma unroll
        for (int j = 0; j < 4; j++)
#pragma unroll
            for (int q = 0; q < 4; q++) acc[i][j][q] = 0.f;

    const int nk = K / KC;
    for (int t = 0; t < nk; t++) {
        const long ko = (long)t * KC;
        CPASYNC16(uAh + d0, pA0h + ko);  CPASYNC16(uAh + d1, pA1h + ko);
        CPASYNC16(uAl + d0, pA0l + ko);  CPASYNC16(uAl + d1, pA1l + ko);
        CPASYNC16(uBh + d0, pB0h + ko);  CPASYNC16(uBh + d1, pB1h + ko);
        CPASYNC16(uBl + d0, pB0l + ko);  CPASYNC16(uBl + d1, pB1l + ko);
        asm volatile("cp.async.commit_group;" ::: "memory");
        asm volatile("cp.async.wait_group 0;" ::: "memory");
        __syncthreads();

#pragma unroll
        for (int kk = 0; kk < 2; kk++) {
            const uint32_t kb = kk * 32;    // 16 bf16 = 32 bytes
            uint32_t af[4][4], bh[2][4], bl[2][4];
#pragma unroll
            for (int ma = 0; ma < 4; ma++)
                LDSM4(af[ma][0], af[ma][1], af[ma][2], af[ma][3],
                      uAh + aoff + ma * 1280u + kb);
#pragma unroll
            for (int g = 0; g < 2; g++) {
                LDSM4(bh[g][0], bh[g][1], bh[g][2], bh[g][3],
                      uBh + boff + g * 1280u + kb);
                LDSM4(bl[g][0], bl[g][1], bl[g][2], bl[g][3],
                      uBl + boff + g * 1280u + kb);
            }
            // terms Ah*Bh and Ah*Bl
#pragma unroll
            for (int ma = 0; ma < 4; ma++)
#pragma unroll
                for (int na = 0; na < 4; na++) {
                    const int g = na >> 1, p = (na & 1) * 2;
                    MMA16816(acc[ma][na], af[ma], bh[g][p], bh[g][p + 1]);
                    MMA16816(acc[ma][na], af[ma], bl[g][p], bl[g][p + 1]);
                }
            // reload Al over af, term Al*Bh
#pragma unroll
            for (int ma = 0; ma < 4; ma++)
                LDSM4(af[ma][0], af[ma][1], af[ma][2], af[ma][3],
                      uAl + aoff + ma * 1280u + kb);
#pragma unroll
            for (int ma = 0; ma < 4; ma++)
#pragma unroll
                for (int na = 0; na < 4; na++) {
                    const int g = na >> 1, p = (na & 1) * 2;
                    MMA16816(acc[ma][na], af[ma], bh[g][p], bh[g][p + 1]);
                }
        }
        __syncthreads();
    }

    // ---- epilogue: acc layout m16n8 -> C
    float* Ch = C + (long)h * NNODE * N;
#pragma unroll
    for (int ma = 0; ma < 4; ma++) {
        const int row = m0 + wm + ma * 16 + (lane >> 2);
#pragma unroll
        for (int na = 0; na < 4; na++) {
            const int col = n0 + wn + na * 8 + (lane & 3) * 2;
            float* p = Ch + (long)row * N + col;
            *(float2*)p             = make_float2(acc[ma][na][0], acc[ma][na][1]);
            *(float2*)(p + 8L * N)  = make_float2(acc[ma][na][2], acc[ma][na][3]);
        }
    }
}

// --------------------------- f1/f2 projections ----------------------------
__global__ __launch_bounds__(256) void f12_k(
    const float* __restrict__ Wh, const float* __restrict__ a, int D)
{
    int lane = threadIdx.x & 31;
    int n = (blockIdx.x * blockDim.x + threadIdx.x) >> 5;
    int h = blockIdx.y;
    if (n >= NNODE) return;
    const float* w  = Wh + ((long)h * NNODE + n) * D;
    const float* ah = a + h * 2 * D;
    float s1 = 0.f, s2 = 0.f;
    for (int d = lane; d < D; d += 32) {
        float v = w[d];
        s1 = fmaf(v, ah[d], s1);
        s2 = fmaf(v, ah[D + d], s2);
    }
    for (int off = 16; off; off >>= 1) {
        s1 += __shfl_down_sync(0xffffffffu, s1, off);
        s2 += __shfl_down_sync(0xffffffffu, s2, off);
    }
    if (lane == 0) { g_f1[h * NNODE + n] = s1; g_f2[h * NNODE + n] = s2; }
}

// column mean of Wh per head (deg==0 fallback) — two-stage reduction
__global__ __launch_bounds__(256) void colmean1_k(const float* __restrict__ Wh, int D)
{
    int chunk = blockIdx.x, h = blockIdx.y;
    const int per = NNODE / CMCH;
    const float* base = Wh + (long)h * NNODE * D + (long)chunk * per * D;
    for (int d = threadIdx.x; d < D; d += 256) {
        float s = 0.f;
        for (int n = 0; n < per; n++) s += base[(long)n * D + d];
        g_cmp[((long)h * CMCH + chunk) * D + d] = s;
    }
}
__global__ __launch_bounds__(256) void colmean2_k(int D)
{
    int d = blockIdx.x * blockDim.x + threadIdx.x;
    int h = blockIdx.y;
    if (d >= D) return;
    float s = 0.f;
    const float* p = g_cmp + (long)h * CMCH * D + d;
    for (int c = 0; c < CMCH; c++) s += p[(long)c * D];
    g_cm[h * D + d] = s * (1.f / NNODE);
}

// ------------------- sparse softmax + aggregate (concat) -------------------
// Writes the next layer's A operand directly as bf16 hi/lo.
__global__ __launch_bounds__(256) void agg_concat_k(
    const float* __restrict__ Wh, int H)
{
    const int D = 256;
    int i = blockIdx.x, h = blockIdx.y, t = threadIdx.x;
    __shared__ float sw[MAXN];
    __shared__ int   snb[MAXN];
    __shared__ float red[256];
    int dg = g_deg[i];
    const int* nb = g_nbr + (long)i * MAXN;
    float f1i = g_f1[h * NNODE + i];
    float lmax = -3.4e38f;
    for (int jj = t; jj < dg; jj += 256) {
        int j = nb[jj];
        snb[jj] = j;
        float e = f1i + g_f2[h * NNODE + j];
        e = e >= 0.f ? e : 0.2f * e;          // leaky_relu(alpha=0.2)
        sw[jj] = e;
        lmax = fmaxf(lmax, e);
    }
    red[t] = lmax; __syncthreads();
    for (int s = 128; s > 0; s >>= 1) { if (t < s) red[t] = fmaxf(red[t], red[t + s]); __syncthreads(); }
    float m = red[0]; __syncthreads();
    float lsum = 0.f;
    for (int jj = t; jj < dg; jj += 256) { float w = expf(sw[jj] - m); sw[jj] = w; lsum += w; }
    red[t] = lsum; __syncthreads();
    for (int s = 128; s > 0; s >>= 1) { if (t < s) red[t] += red[t + s]; __syncthreads(); }
    float inv = 1.f / red[0]; __syncthreads();

    float acc;
    if (dg > 0) {
        const float* whh = Wh + (long)h * NNODE * D;
        float a0 = 0.f, a1 = 0.f, a2 = 0.f, a3 = 0.f;
        int jj = 0;
        for (; jj + 4 <= dg; jj += 4) {
            a0 = fmaf(sw[jj + 0], (whh + (long)snb[jj + 0] * D)[t], a0);
            a1 = fmaf(sw[jj + 1], (whh + (long)snb[jj + 1] * D)[t], a1);
            a2 = fmaf(sw[jj + 2], (whh + (long)snb[jj + 2] * D)[t], a2);
            a3 = fmaf(sw[jj + 3], (whh + (long)snb[jj + 3] * D)[t], a3);
        }
        for (; jj < dg; jj++) a0 = fmaf(sw[jj], (whh + (long)snb[jj] * D)[t], a0);
        acc = ((a0 + a1) + (a2 + a3)) * inv;
    } else {
        acc = g_cm[h * D + t];                // uniform softmax over all nodes
    }
    acc = eluf(eluf(acc));                    // reference applies elu twice
    __nv_bfloat16 hv = __float2bfloat16(acc);
    long o = (long)i * (H * D) + h * D + t;
    g_Ah[o] = hv;
    g_Al[o] = __float2bfloat16(acc - __bfloat162float(hv));
}

// ------------- output layer: 6 heads, mean, elu, L2-normalize -------------
__global__ __launch_bounds__(256) void agg_mean_norm_k(
    const float* __restrict__ Wh, float* __restrict__ out)
{
    const int D = 512;
    int i = blockIdx.x, t = threadIdx.x;
    __shared__ float sw[MAXN];
    __shared__ int   snb[MAXN];
    __shared__ float red[256];
    int dg = g_deg[i];
    const int* nb = g_nbr + (long)i * MAXN;
    for (int jj = t; jj < dg; jj += 256) snb[jj] = nb[jj];
    __syncthreads();

    float acc0 = 0.f, acc1 = 0.f;
    for (int h = 0; h < 6; h++) {
        float f1i = g_f1[h * NNODE + i];
        float lmax = -3.4e38f;
        for (int jj = t; jj < dg; jj += 256) {
            float e = f1i + g_f2[h * NNODE + snb[jj]];
            e = e >= 0.f ? e : 0.2f * e;
            sw[jj] = e;
            lmax = fmaxf(lmax, e);
        }
        red[t] = lmax; __syncthreads();
        for (int s = 128; s > 0; s >>= 1) { if (t < s) red[t] = fmaxf(red[t], red[t + s]); __syncthreads(); }
        float m = red[0]; __syncthreads();
        float lsum = 0.f;
        for (int jj = t; jj < dg; jj += 256) { float w = expf(sw[jj] - m); sw[jj] = w; lsum += w; }
        red[t] = lsum; __syncthreads();
        for (int s = 128; s > 0; s >>= 1) { if (t < s) red[t] += red[t + s]; __syncthreads(); }
        float inv = 1.f / red[0]; __syncthreads();

        if (dg > 0) {
            const float* whh = Wh + (long)h * NNODE * D;
            float a0 = 0.f, a1 = 0.f;
            for (int jj = 0; jj < dg; jj++) {
                const float* r = whh + (long)snb[jj] * D;
                float w = sw[jj];
                a0 = fmaf(w, r[t], a0);
                a1 = fmaf(w, r[t + 256], a1);
            }
            acc0 += a0 * inv;
            acc1 += a1 * inv;
        } else {
            acc0 += g_cm[h * D + t];
            acc1 += g_cm[h * D + t + 256];
        }
        __syncthreads();
    }
    acc0 *= (1.f / 6.f); acc1 *= (1.f / 6.f);
    acc0 = eluf(acc0);   acc1 = eluf(acc1);
    red[t] = acc0 * acc0 + acc1 * acc1; __syncthreads();
    for (int s = 128; s > 0; s >>= 1) { if (t < s) red[t] += red[t + s]; __syncthreads(); }
    float nrm = sqrtf(red[0]);
    float inv2 = 1.f / fmaxf(nrm, 1e-12f);
    out[(long)i * D + t]       = acc0 * inv2;
    out[(long)i * D + t + 256] = acc1 * inv2;
}

// ------------------------------- launcher ----------------------------------
extern "C" void kernel_launch(void* const* d_in, const int* in_sizes, int n_in,
                              void* d_out, int out_size) {
    const float* x   = (const float*)d_in[0];   // [4096, 2048]
    const float* adj = (const float*)d_in[1];   // [4096, 4096]
    const float* W1  = (const float*)d_in[2];   // [4, 2048, 256]
    const float* a1  = (const float*)d_in[3];   // [4, 512]
    const float* W2  = (const float*)d_in[4];   // [4, 1024, 256]
    const float* a2  = (const float*)d_in[5];   // [4, 512]
    const float* W3  = (const float*)d_in[6];   // [6, 1024, 512]
    const float* a3  = (const float*)d_in[7];   // [6, 1024]
    float* out = (float*)d_out;                 // [4096, 512]

    float* pWh = nullptr;
    __nv_bfloat16 *pAh = nullptr, *pAl = nullptr, *pBh = nullptr, *pBl = nullptr;
    cudaGetSymbolAddress((void**)&pWh, g_Wh);
    cudaGetSymbolAddress((void**)&pAh, g_Ah);
    cudaGetSymbolAddress((void**)&pAl, g_Al);
    cudaGetSymbolAddress((void**)&pBh, g_Bh);
    cudaGetSymbolAddress((void**)&pBl, g_Bl);

    build_nbr_k<<<512, 256>>>(adj);

    // ---- layer 1: H=4, K=2048, N(out)=256 ----
    split_x_k<<<4096, 256>>>(x, 4096L * 2048);
    wsplit_k<<<dim3(64, 8, 4), 256>>>(W1, 2048, 256);
    mma_gemm_k<<<dim3(2, 32, 4), 256>>>(pAh, pAl, pBh, pBl, pWh, 2048, 256);
    f12_k<<<dim3(512, 4), 256>>>(pWh, a1, 256);
    colmean1_k<<<dim3(CMCH, 4), 256>>>(pWh, 256);
    colmean2_k<<<dim3(1, 4), 256>>>(256);
    agg_concat_k<<<dim3(NNODE, 4), 256>>>(pWh, 4);   // writes g_Ah/g_Al [4096,1024]

    // ---- layer 2: H=4, K=1024, N(out)=256 ----
    wsplit_k<<<dim3(32, 8, 4), 256>>>(W2, 1024, 256);
    mma_gemm_k<<<dim3(2, 32, 4), 256>>>(pAh, pAl, pBh, pBl, pWh, 1024, 256);
    f12_k<<<dim3(512, 4), 256>>>(pWh, a2, 256);
    colmean1_k<<<dim3(CMCH, 4), 256>>>(pWh, 256);
    colmean2_k<<<dim3(1, 4), 256>>>(256);
    agg_concat_k<<<dim3(NNODE, 4), 256>>>(pWh, 4);   // writes g_Ah/g_Al [4096,1024]

    // ---- output layer: H=6, K=1024, N(out)=512, mean+elu+normalize ----
    wsplit_k<<<dim3(32, 16, 6), 256>>>(W3, 1024, 512);
    mma_gemm_k<<<dim3(4, 32, 6), 256>>>(pAh, pAl, pBh, pBl, pWh, 1024, 512);
    f12_k<<<dim3(512, 6), 256>>>(pWh, a3, 512);
    colmean1_k<<<dim3(CMCH, 6), 256>>>(pWh, 512);
    colmean2_k<<<dim3(2, 6), 256>>>(512);
    agg_mean_norm_k<<<NNODE, 256>>>(pWh, out);
}

// round 15
// speedup vs baseline: 1.9348x; 1.0232x over previous
#include <cuda_runtime.h>
#include <cuda_bf16.h>
#include <math.h>
#include <stdint.h>

// ---------------------------------------------------------------------------
// GAT, N=4096, NFEAT=2048, D=256, NCLASS=512, heads 4/4/6, alpha=0.2
// Sparse attention (adjacency ~1% -> neighbor lists).
// Projections via warp-level mma.sync bf16 (m16n8k16) with 3-term hi/lo split
// (fp32-accurate), 2-stage cp.async pipelined smem.
// (tcgen05 unavailable: harness PTX targets sm_103 baseline ISA.)
// ---------------------------------------------------------------------------

#define NNODE 4096
#define MAXN  1024

// Scratch (device globals)
__device__ float g_Wh[6L * 4096 * 512];                       // projections fp32
__device__ __align__(16) __nv_bfloat16 g_Ah[4096L * 2048];    // A operand hi
__device__ __align__(16) __nv_bfloat16 g_Al[4096L * 2048];    // A operand lo
__device__ __align__(16) __nv_bfloat16 g_Bh[6L * 512 * 1024]; // W^T hi [H][N][K]
__device__ __align__(16) __nv_bfloat16 g_Bl[6L * 512 * 1024]; // W^T lo
__device__ float g_f1[6 * 4096];
__device__ float g_f2[6 * 4096];
__device__ float g_cm[6 * 512];
#define CMCH 32
__device__ float g_cmp[6L * CMCH * 512];
__device__ int   g_nbr[4096L * MAXN];
__device__ int   g_deg[4096];

__device__ __forceinline__ float eluf(float x) { return x > 0.f ? x : expm1f(x); }

__device__ __forceinline__ uint32_t smem_to_u32(const void* p) {
    uint32_t a;
    asm("{ .reg .u64 t; cvta.to.shared.u64 t, %1; cvt.u32.u64 %0, t; }"
        : "=r"(a) : "l"(p));
    return a;
}
#define CPASYNC16(dst, src) \
    asm volatile("cp.async.cg.shared.global [%0], [%1], 16;" \
        :: "r"((uint32_t)(dst)), "l"(src) : "memory")
#define LDSM4(R0, R1, R2, R3, ADDR) \
    asm volatile("ldmatrix.sync.aligned.m8n8.x4.shared.b16 {%0,%1,%2,%3}, [%4];" \
        : "=r"(R0), "=r"(R1), "=r"(R2), "=r"(R3) : "r"(ADDR))
#define MMA16816(C, A, B0, B1) \
    asm volatile("mma.sync.aligned.m16n8k16.row.col.f32.bf16.bf16.f32 " \
        "{%0,%1,%2,%3}, {%4,%5,%6,%7}, {%8,%9}, {%0,%1,%2,%3};" \
        : "+f"((C)[0]), "+f"((C)[1]), "+f"((C)[2]), "+f"((C)[3]) \
        : "r"((A)[0]), "r"((A)[1]), "r"((A)[2]), "r"((A)[3]), \
          "r"(B0), "r"(B1))

// --------------------------- neighbor-list build ---------------------------
__global__ __launch_bounds__(256) void build_nbr_k(const float* __restrict__ adj) {
    int warp = (blockIdx.x * blockDim.x + threadIdx.x) >> 5;
    int lane = threadIdx.x & 31;
    if (warp >= NNODE) return;
    const float* row = adj + (long)warp * NNODE;
    int* dst = g_nbr + (long)warp * MAXN;
    int base = 0;
    for (int j0 = 0; j0 < NNODE; j0 += 32) {
        float v = row[j0 + lane];
        unsigned m = __ballot_sync(0xffffffffu, v > 0.f);
        if (v > 0.f) {
            int pos = base + __popc(m & ((1u << lane) - 1u));
            if (pos < MAXN) dst[pos] = j0 + lane;
        }
        base += __popc(m);
    }
    if (lane == 0) g_deg[warp] = min(base, MAXN);
}

// ------------------------- fp32 -> bf16 hi/lo split ------------------------
__global__ __launch_bounds__(256) void split_x_k(const float* __restrict__ x, long n) {
    long i = (long)blockIdx.x * blockDim.x + threadIdx.x;
    long stride = (long)gridDim.x * blockDim.x;
    for (; i < n; i += stride) {
        float v = x[i];
        __nv_bfloat16 h = __float2bfloat16(v);
        g_Ah[i] = h;
        g_Al[i] = __float2bfloat16(v - __bfloat162float(h));
    }
}

// W [H][K][N] fp32 -> Bh/Bl [H][N][K] bf16 (32x32 smem-tile transpose)
__global__ __launch_bounds__(256) void wsplit_k(const float* __restrict__ W, int K, int N) {
    __shared__ float tile[32][33];
    int h = blockIdx.z;
    int k0 = blockIdx.x * 32, n0 = blockIdx.y * 32;
    int tx = threadIdx.x & 31, ty = threadIdx.x >> 5;   // 32 x 8
    const float* Wp = W + (long)h * K * N;
#pragma unroll
    for (int i = 0; i < 4; i++)
        tile[ty + i * 8][tx] = Wp[(long)(k0 + ty + i * 8) * N + n0 + tx];
    __syncthreads();
#pragma unroll
    for (int i = 0; i < 4; i++) {
        int n = n0 + ty + i * 8, k = k0 + tx;
        float v = tile[tx][ty + i * 8];
        __nv_bfloat16 hv = __float2bfloat16(v);
        long o = ((long)h * N + n) * K + k;
        g_Bh[o] = hv;
        g_Bl[o] = __float2bfloat16(v - __bfloat162float(hv));
    }
}

// -------------------- warp-MMA GEMM (3-term bf16 split) --------------------
// C[h] = A @ B[h]^T; A hi/lo: [4096,K] bf16; B hi/lo: [H][N][K] bf16 (K-major)
// C: [H][4096][N] fp32. CTA tile 128x128, 8 warps (2x4), warp tile 64x32.
// K-chunk 32; 2-stage cp.async pipeline (loads of chunk t+1 overlap MMA of t).
#define KC 32
#define PB 40                         // smem row pitch in bf16 (80 B)
#define REG_BYTES (128 * PB * 2)      // one operand tile: 10240 B
#define STAGE_BYTES (4 * REG_BYTES)   // Ah/Al/Bh/Bl: 40960 B
#define GEMM_SMEM (2 * STAGE_BYTES)   // 81920 B

__global__ void __launch_bounds__(256, 2) mma_gemm_k(
    const __nv_bfloat16* __restrict__ Ah, const __nv_bfloat16* __restrict__ Al,
    const __nv_bfloat16* __restrict__ Bh, const __nv_bfloat16* __restrict__ Bl,
    float* __restrict__ C, int K, int N)
{
    extern __shared__ __align__(16) char dsm[];
    const uint32_t base = smem_to_u32(dsm);

    const int tid = threadIdx.x, lane = tid & 31, wid = tid >> 5;
    const int m0 = blockIdx.y * 128, n0 = blockIdx.x * 128, h = blockIdx.z;
    const int wm = (wid & 1) * 64;        // warp m offset
    const int wn = (wid >> 1) * 32;       // warp n offset

    // ---- global->smem chunk mapping: 512 16B-chunks per tile, 2 per thread
    const int r0 = tid >> 2, s0 = (tid & 3);
    const int r1 = (tid + 256) >> 2, s1 = ((tid + 256) & 3);
    const uint32_t d0 = (uint32_t)r0 * 80u + (uint32_t)s0 * 16u;
    const uint32_t d1 = (uint32_t)r1 * 80u + (uint32_t)s1 * 16u;
    const __nv_bfloat16* pA0h = Ah + (long)(m0 + r0) * K + s0 * 8;
    const __nv_bfloat16* pA1h = Ah + (long)(m0 + r1) * K + s1 * 8;
    const __nv_bfloat16* pA0l = Al + (long)(m0 + r0) * K + s0 * 8;
    const __nv_bfloat16* pA1l = Al + (long)(m0 + r1) * K + s1 * 8;
    const __nv_bfloat16* pB0h = Bh + ((long)h * N + n0 + r0) * K + s0 * 8;
    const __nv_bfloat16* pB1h = Bh + ((long)h * N + n0 + r1) * K + s1 * 8;
    const __nv_bfloat16* pB0l = Bl + ((long)h * N + n0 + r0) * K + s0 * 8;
    const __nv_bfloat16* pB1l = Bl + ((long)h * N + n0 + r1) * K + s1 * 8;

    // ---- ldmatrix lane address offsets (bytes, within one operand tile)
    const uint32_t aoff = (uint32_t)(wm + (lane & 15)) * 80u + (uint32_t)(lane >> 4) * 16u;
    const uint32_t boff = (uint32_t)(wn + (lane & 7) + ((lane >> 4) << 3)) * 80u
                        + (uint32_t)((lane >> 3) & 1) * 16u;

    float acc[4][4][4];
#pragma unroll
    for (int i = 0; i < 4; i++)
#pragma unroll
        for (int j = 0; j < 4; j++)
#pragma unroll
            for (int q = 0; q < 4; q++) acc[i][j][q] = 0.f;

    const int nk = K / KC;

#define ISSUE_STAGE(T) do {                                              \
        const uint32_t sb = base + ((T) & 1) * STAGE_BYTES;              \
        const long ko = (long)(T) * KC;                                  \
        CPASYNC16(sb + d0, pA0h + ko);                                   \
        CPASYNC16(sb + d1, pA1h + ko);                                   \
        CPASYNC16(sb + REG_BYTES + d0, pA0l + ko);                       \
        CPASYNC16(sb + REG_BYTES + d1, pA1l + ko);                       \
        CPASYNC16(sb + 2 * REG_BYTES + d0, pB0h + ko);                   \
        CPASYNC16(sb + 2 * REG_BYTES + d1, pB1h + ko);                   \
        CPASYNC16(sb + 3 * REG_BYTES + d0, pB0l + ko);                   \
        CPASYNC16(sb + 3 * REG_BYTES + d1, pB1l + ko);                   \
        asm volatile("cp.async.commit_group;" ::: "memory");             \
    } while (0)

    ISSUE_STAGE(0);

    for (int t = 0; t < nk; t++) {
        if (t + 1 < nk) {
            ISSUE_STAGE(t + 1);
            asm volatile("cp.async.wait_group 1;" ::: "memory");
        } else {
            asm volatile("cp.async.wait_group 0;" ::: "memory");
        }
        __syncthreads();

        const uint32_t sb  = base + (t & 1) * STAGE_BYTES;
        const uint32_t uAh = sb;
        const uint32_t uAl = sb + REG_BYTES;
        const uint32_t uBh = sb + 2 * REG_BYTES;
        const uint32_t uBl = sb + 3 * REG_BYTES;

#pragma unroll
        for (int kk = 0; kk < 2; kk++) {
            const uint32_t kb = kk * 32;    // 16 bf16 = 32 bytes
            uint32_t af[4][4], bh[2][4], bl[2][4];
#pragma unroll
            for (int ma = 0; ma < 4; ma++)
                LDSM4(af[ma][0], af[ma][1], af[ma][2], af[ma][3],
                      uAh + aoff + ma * 1280u + kb);
#pragma unroll
            for (int g = 0; g < 2; g++) {
                LDSM4(bh[g][0], bh[g][1], bh[g][2], bh[g][3],
                      uBh + boff + g * 1280u + kb);
                LDSM4(bl[g][0], bl[g][1], bl[g][2], bl[g][3],
                      uBl + boff + g * 1280u + kb);
            }
            // terms Ah*Bh and Ah*Bl
#pragma unroll
            for (int ma = 0; ma < 4; ma++)
#pragma unroll
                for (int na = 0; na < 4; na++) {
                    const int g = na >> 1, p = (na & 1) * 2;
                    MMA16816(acc[ma][na], af[ma], bh[g][p], bh[g][p + 1]);
                    MMA16816(acc[ma][na], af[ma], bl[g][p], bl[g][p + 1]);
                }
            // reload Al over af, term Al*Bh
#pragma unroll
            for (int ma = 0; ma < 4; ma++)
                LDSM4(af[ma][0], af[ma][1], af[ma][2], af[ma][3],
                      uAl + aoff + ma * 1280u + kb);
#pragma unroll
            for (int ma = 0; ma < 4; ma++)
#pragma unroll
                for (int na = 0; na < 4; na++) {
                    const int g = na >> 1, p = (na & 1) * 2;
                    MMA16816(acc[ma][na], af[ma], bh[g][p], bh[g][p + 1]);
                }
        }
        __syncthreads();
    }
#undef ISSUE_STAGE

    // ---- epilogue: acc layout m16n8 -> C
    float* Ch = C + (long)h * NNODE * N;
#pragma unroll
    for (int ma = 0; ma < 4; ma++) {
        const int row = m0 + wm + ma * 16 + (lane >> 2);
#pragma unroll
        for (int na = 0; na < 4; na++) {
            const int col = n0 + wn + na * 8 + (lane & 3) * 2;
            float* p = Ch + (long)row * N + col;
            *(float2*)p             = make_float2(acc[ma][na][0], acc[ma][na][1]);
            *(float2*)(p + 8L * N)  = make_float2(acc[ma][na][2], acc[ma][na][3]);
        }
    }
}

// --------------------------- f1/f2 projections ----------------------------
__global__ __launch_bounds__(256) void f12_k(
    const float* __restrict__ Wh, const float* __restrict__ a, int D)
{
    int lane = threadIdx.x & 31;
    int n = (blockIdx.x * blockDim.x + threadIdx.x) >> 5;
    int h = blockIdx.y;
    if (n >= NNODE) return;
    const float* w  = Wh + ((long)h * NNODE + n) * D;
    const float* ah = a + h * 2 * D;
    float s1 = 0.f, s2 = 0.f;
    for (int d = lane; d < D; d += 32) {
        float v = w[d];
        s1 = fmaf(v, ah[d], s1);
        s2 = fmaf(v, ah[D + d], s2);
    }
    for (int off = 16; off; off >>= 1) {
        s1 += __shfl_down_sync(0xffffffffu, s1, off);
        s2 += __shfl_down_sync(0xffffffffu, s2, off);
    }
    if (lane == 0) { g_f1[h * NNODE + n] = s1; g_f2[h * NNODE + n] = s2; }
}

// column mean of Wh per head (deg==0 fallback) — two-stage reduction
__global__ __launch_bounds__(256) void colmean1_k(const float* __restrict__ Wh, int D)
{
    int chunk = blockIdx.x, h = blockIdx.y;
    const int per = NNODE / CMCH;
    const float* base = Wh + (long)h * NNODE * D + (long)chunk * per * D;
    for (int d = threadIdx.x; d < D; d += 256) {
        float s = 0.f;
        for (int n = 0; n < per; n++) s += base[(long)n * D + d];
        g_cmp[((long)h * CMCH + chunk) * D + d] = s;
    }
}
__global__ __launch_bounds__(256) void colmean2_k(int D)
{
    int d = blockIdx.x * blockDim.x + threadIdx.x;
    int h = blockIdx.y;
    if (d >= D) return;
    float s = 0.f;
    const float* p = g_cmp + (long)h * CMCH * D + d;
    for (int c = 0; c < CMCH; c++) s += p[(long)c * D];
    g_cm[h * D + d] = s * (1.f / NNODE);
}

// ------------------- sparse softmax + aggregate (concat) -------------------
// Writes the next layer's A operand directly as bf16 hi/lo.
__global__ __launch_bounds__(256) void agg_concat_k(
    const float* __restrict__ Wh, int H)
{
    const int D = 256;
    int i = blockIdx.x, h = blockIdx.y, t = threadIdx.x;
    __shared__ float sw[MAXN];
    __shared__ int   snb[MAXN];
    __shared__ float red[256];
    int dg = g_deg[i];
    const int* nb = g_nbr + (long)i * MAXN;
    float f1i = g_f1[h * NNODE + i];
    float lmax = -3.4e38f;
    for (int jj = t; jj < dg; jj += 256) {
        int j = nb[jj];
        snb[jj] = j;
        float e = f1i + g_f2[h * NNODE + j];
        e = e >= 0.f ? e : 0.2f * e;          // leaky_relu(alpha=0.2)
        sw[jj] = e;
        lmax = fmaxf(lmax, e);
    }
    red[t] = lmax; __syncthreads();
    for (int s = 128; s > 0; s >>= 1) { if (t < s) red[t] = fmaxf(red[t], red[t + s]); __syncthreads(); }
    float m = red[0]; __syncthreads();
    float lsum = 0.f;
    for (int jj = t; jj < dg; jj += 256) { float w = expf(sw[jj] - m); sw[jj] = w; lsum += w; }
    red[t] = lsum; __syncthreads();
    for (int s = 128; s > 0; s >>= 1) { if (t < s) red[t] += red[t + s]; __syncthreads(); }
    float inv = 1.f / red[0]; __syncthreads();

    float acc;
    if (dg > 0) {
        const float* whh = Wh + (long)h * NNODE * D;
        float a0 = 0.f, a1 = 0.f, a2 = 0.f, a3 = 0.f;
        int jj = 0;
        for (; jj + 4 <= dg; jj += 4) {
            a0 = fmaf(sw[jj + 0], (whh + (long)snb[jj + 0] * D)[t], a0);
            a1 = fmaf(sw[jj + 1], (whh + (long)snb[jj + 1] * D)[t], a1);
            a2 = fmaf(sw[jj + 2], (whh + (long)snb[jj + 2] * D)[t], a2);
            a3 = fmaf(sw[jj + 3], (whh + (long)snb[jj + 3] * D)[t], a3);
        }
        for (; jj < dg; jj++) a0 = fmaf(sw[jj], (whh + (long)snb[jj] * D)[t], a0);
        acc = ((a0 + a1) + (a2 + a3)) * inv;
    } else {
        acc = g_cm[h * D + t];                // uniform softmax over all nodes
    }
    acc = eluf(eluf(acc));                    // reference applies elu twice
    __nv_bfloat16 hv = __float2bfloat16(acc);
    long o = (long)i * (H * D) + h * D + t;
    g_Ah[o] = hv;
    g_Al[o] = __float2bfloat16(acc - __bfloat162float(hv));
}

// ------------- output layer: 6 heads, mean, elu, L2-normalize -------------
__global__ __launch_bounds__(256) void agg_mean_norm_k(
    const float* __restrict__ Wh, float* __restrict__ out)
{
    const int D = 512;
    int i = blockIdx.x, t = threadIdx.x;
    __shared__ float sw[MAXN];
    __shared__ int   snb[MAXN];
    __shared__ float red[256];
    int dg = g_deg[i];
    const int* nb = g_nbr + (long)i * MAXN;
    for (int jj = t; jj < dg; jj += 256) snb[jj] = nb[jj];
    __syncthreads();

    float acc0 = 0.f, acc1 = 0.f;
    for (int h = 0; h < 6; h++) {
        float f1i = g_f1[h * NNODE + i];
        float lmax = -3.4e38f;
        for (int jj = t; jj < dg; jj += 256) {
            float e = f1i + g_f2[h * NNODE + snb[jj]];
            e = e >= 0.f ? e : 0.2f * e;
            sw[jj] = e;
            lmax = fmaxf(lmax, e);
        }
        red[t] = lmax; __syncthreads();
        for (int s = 128; s > 0; s >>= 1) { if (t < s) red[t] = fmaxf(red[t], red[t + s]); __syncthreads(); }
        float m = red[0]; __syncthreads();
        float lsum = 0.f;
        for (int jj = t; jj < dg; jj += 256) { float w = expf(sw[jj] - m); sw[jj] = w; lsum += w; }
        red[t] = lsum; __syncthreads();
        for (int s = 128; s > 0; s >>= 1) { if (t < s) red[t] += red[t + s]; __syncthreads(); }
        float inv = 1.f / red[0]; __syncthreads();

        if (dg > 0) {
            const float* whh = Wh + (long)h * NNODE * D;
            float a0 = 0.f, a1 = 0.f, b0 = 0.f, b1 = 0.f;
            int jj = 0;
            for (; jj + 2 <= dg; jj += 2) {
                const float* ra = whh + (long)snb[jj] * D;
                const float* rb = whh + (long)snb[jj + 1] * D;
                float wa = sw[jj], wb = sw[jj + 1];
                a0 = fmaf(wa, ra[t], a0);
                a1 = fmaf(wa, ra[t + 256], a1);
                b0 = fmaf(wb, rb[t], b0);
                b1 = fmaf(wb, rb[t + 256], b1);
            }
            if (jj < dg) {
                const float* ra = whh + (long)snb[jj] * D;
                float wa = sw[jj];
                a0 = fmaf(wa, ra[t], a0);
                a1 = fmaf(wa, ra[t + 256], a1);
            }
            acc0 += (a0 + b0) * inv;
            acc1 += (a1 + b1) * inv;
        } else {
            acc0 += g_cm[h * D + t];
            acc1 += g_cm[h * D + t + 256];
        }
        __syncthreads();   // sw reused next head
    }
    acc0 *= (1.f / 6.f); acc1 *= (1.f / 6.f);
    acc0 = eluf(acc0);   acc1 = eluf(acc1);
    red[t] = acc0 * acc0 + acc1 * acc1; __syncthreads();
    for (int s = 128; s > 0; s >>= 1) { if (t < s) red[t] += red[t + s]; __syncthreads(); }
    float nrm = sqrtf(red[0]);
    float inv2 = 1.f / fmaxf(nrm, 1e-12f);
    out[(long)i * D + t]       = acc0 * inv2;
    out[(long)i * D + t + 256] = acc1 * inv2;
}

// ------------------------------- launcher ----------------------------------
extern "C" void kernel_launch(void* const* d_in, const int* in_sizes, int n_in,
                              void* d_out, int out_size) {
    const float* x   = (const float*)d_in[0];   // [4096, 2048]
    const float* adj = (const float*)d_in[1];   // [4096, 4096]
    const float* W1  = (const float*)d_in[2];   // [4, 2048, 256]
    const float* a1  = (const float*)d_in[3];   // [4, 512]
    const float* W2  = (const float*)d_in[4];   // [4, 1024, 256]
    const float* a2  = (const float*)d_in[5];   // [4, 512]
    const float* W3  = (const float*)d_in[6];   // [6, 1024, 512]
    const float* a3  = (const float*)d_in[7];   // [6, 1024]
    float* out = (float*)d_out;                 // [4096, 512]

    static int attr_set = 0;
    if (!attr_set) {
        cudaFuncSetAttribute(mma_gemm_k,
                             cudaFuncAttributeMaxDynamicSharedMemorySize, GEMM_SMEM);
        attr_set = 1;
    }

    float* pWh = nullptr;
    __nv_bfloat16 *pAh = nullptr, *pAl = nullptr, *pBh = nullptr, *pBl = nullptr;
    cudaGetSymbolAddress((void**)&pWh, g_Wh);
    cudaGetSymbolAddress((void**)&pAh, g_Ah);
    cudaGetSymbolAddress((void**)&pAl, g_Al);
    cudaGetSymbolAddress((void**)&pBh, g_Bh);
    cudaGetSymbolAddress((void**)&pBl, g_Bl);

    build_nbr_k<<<512, 256>>>(adj);

    // ---- layer 1: H=4, K=2048, N(out)=256 ----
    split_x_k<<<4096, 256>>>(x, 4096L * 2048);
    wsplit_k<<<dim3(64, 8, 4), 256>>>(W1, 2048, 256);
    mma_gemm_k<<<dim3(2, 32, 4), 256, GEMM_SMEM>>>(pAh, pAl, pBh, pBl, pWh, 2048, 256);
    f12_k<<<dim3(512, 4), 256>>>(pWh, a1, 256);
    colmean1_k<<<dim3(CMCH, 4), 256>>>(pWh, 256);
    colmean2_k<<<dim3(1, 4), 256>>>(256);
    agg_concat_k<<<dim3(NNODE, 4), 256>>>(pWh, 4);   // writes g_Ah/g_Al [4096,1024]

    // ---- layer 2: H=4, K=1024, N(out)=256 ----
    wsplit_k<<<dim3(32, 8, 4), 256>>>(W2, 1024, 256);
    mma_gemm_k<<<dim3(2, 32, 4), 256, GEMM_SMEM>>>(pAh, pAl, pBh, pBl, pWh, 1024, 256);
    f12_k<<<dim3(512, 4), 256>>>(pWh, a2, 256);
    colmean1_k<<<dim3(CMCH, 4), 256>>>(pWh, 256);
    colmean2_k<<<dim3(1, 4), 256>>>(256);
    agg_concat_k<<<dim3(NNODE, 4), 256>>>(pWh, 4);   // writes g_Ah/g_Al [4096,1024]

    // ---- output layer: H=6, K=1024, N(out)=512, mean+elu+normalize ----
    wsplit_k<<<dim3(32, 16, 6), 256>>>(W3, 1024, 512);
    mma_gemm_k<<<dim3(4, 32, 6), 256, GEMM_SMEM>>>(pAh, pAl, pBh, pBl, pWh, 1024, 512);
    f12_k<<<dim3(512, 6), 256>>>(pWh, a3, 512);
    colmean1_k<<<dim3(CMCH, 6), 256>>>(pWh, 512);
    colmean2_k<<<dim3(2, 6), 256>>>(512);
    agg_mean_norm_k<<<NNODE, 256>>>(pWh, out);
}

// round 16
// speedup vs baseline: 1.9399x; 1.0026x over previous
#include <cuda_runtime.h>
#include <cuda_bf16.h>
#include <math.h>
#include <stdint.h>

// ---------------------------------------------------------------------------
// GAT, N=4096, NFEAT=2048, D=256, NCLASS=512, heads 4/4/6, alpha=0.2
// Sparse attention (adjacency ~1% -> neighbor lists).
// Projections via warp-level mma.sync bf16 (m16n8k16) with 3-term hi/lo split
// (fp32-accurate), 2-stage cp.async pipeline, term-major MMA ordering to
// break accumulator RAW chains.
// ---------------------------------------------------------------------------

#define NNODE 4096
#define MAXN  1024

// Scratch (device globals)
__device__ float g_Wh[6L * 4096 * 512];                       // projections fp32
__device__ __align__(16) __nv_bfloat16 g_Ah[4096L * 2048];    // A operand hi
__device__ __align__(16) __nv_bfloat16 g_Al[4096L * 2048];    // A operand lo
__device__ __align__(16) __nv_bfloat16 g_Bh[6L * 512 * 1024]; // W^T hi [H][N][K]
__device__ __align__(16) __nv_bfloat16 g_Bl[6L * 512 * 1024]; // W^T lo
__device__ float g_f1[6 * 4096];
__device__ float g_f2[6 * 4096];
__device__ float g_cm[6 * 512];
#define CMCH 32
__device__ float g_cmp[6L * CMCH * 512];
__device__ int   g_nbr[4096L * MAXN];
__device__ int   g_deg[4096];

__device__ __forceinline__ float eluf(float x) { return x > 0.f ? x : expm1f(x); }

__device__ __forceinline__ uint32_t smem_to_u32(const void* p) {
    uint32_t a;
    asm("{ .reg .u64 t; cvta.to.shared.u64 t, %1; cvt.u32.u64 %0, t; }"
        : "=r"(a) : "l"(p));
    return a;
}
#define CPASYNC16(dst, src) \
    asm volatile("cp.async.cg.shared.global [%0], [%1], 16;" \
        :: "r"((uint32_t)(dst)), "l"(src) : "memory")
#define LDSM4(R0, R1, R2, R3, ADDR) \
    asm volatile("ldmatrix.sync.aligned.m8n8.x4.shared.b16 {%0,%1,%2,%3}, [%4];" \
        : "=r"(R0), "=r"(R1), "=r"(R2), "=r"(R3) : "r"(ADDR))
#define MMA16816(C, A, B0, B1) \
    asm volatile("mma.sync.aligned.m16n8k16.row.col.f32.bf16.bf16.f32 " \
        "{%0,%1,%2,%3}, {%4,%5,%6,%7}, {%8,%9}, {%0,%1,%2,%3};" \
        : "+f"((C)[0]), "+f"((C)[1]), "+f"((C)[2]), "+f"((C)[3]) \
        : "r"((A)[0]), "r"((A)[1]), "r"((A)[2]), "r"((A)[3]), \
          "r"(B0), "r"(B1))

// --------------------------- neighbor-list build ---------------------------
__global__ __launch_bounds__(256) void build_nbr_k(const float* __restrict__ adj) {
    int warp = (blockIdx.x * blockDim.x + threadIdx.x) >> 5;
    int lane = threadIdx.x & 31;
    if (warp >= NNODE) return;
    const float* row = adj + (long)warp * NNODE;
    int* dst = g_nbr + (long)warp * MAXN;
    int base = 0;
    for (int j0 = 0; j0 < NNODE; j0 += 32) {
        float v = row[j0 + lane];
        unsigned m = __ballot_sync(0xffffffffu, v > 0.f);
        if (v > 0.f) {
            int pos = base + __popc(m & ((1u << lane) - 1u));
            if (pos < MAXN) dst[pos] = j0 + lane;
        }
        base += __popc(m);
    }
    if (lane == 0) g_deg[warp] = min(base, MAXN);
}

// ------------------------- fp32 -> bf16 hi/lo split ------------------------
__global__ __launch_bounds__(256) void split_x_k(const float* __restrict__ x, long n) {
    long i = (long)blockIdx.x * blockDim.x + threadIdx.x;
    long stride = (long)gridDim.x * blockDim.x;
    for (; i < n; i += stride) {
        float v = x[i];
        __nv_bfloat16 h = __float2bfloat16(v);
        g_Ah[i] = h;
        g_Al[i] = __float2bfloat16(v - __bfloat162float(h));
    }
}

// W [H][K][N] fp32 -> Bh/Bl [H][N][K] bf16 (32x32 smem-tile transpose)
__global__ __launch_bounds__(256) void wsplit_k(const float* __restrict__ W, int K, int N) {
    __shared__ float tile[32][33];
    int h = blockIdx.z;
    int k0 = blockIdx.x * 32, n0 = blockIdx.y * 32;
    int tx = threadIdx.x & 31, ty = threadIdx.x >> 5;   // 32 x 8
    const float* Wp = W + (long)h * K * N;
#pragma unroll
    for (int i = 0; i < 4; i++)
        tile[ty + i * 8][tx] = Wp[(long)(k0 + ty + i * 8) * N + n0 + tx];
    __syncthreads();
#pragma unroll
    for (int i = 0; i < 4; i++) {
        int n = n0 + ty + i * 8, k = k0 + tx;
        float v = tile[tx][ty + i * 8];
        __nv_bfloat16 hv = __float2bfloat16(v);
        long o = ((long)h * N + n) * K + k;
        g_Bh[o] = hv;
        g_Bl[o] = __float2bfloat16(v - __bfloat162float(hv));
    }
}

// -------------------- warp-MMA GEMM (3-term bf16 split) --------------------
// C[h] = A @ B[h]^T; A hi/lo: [4096,K] bf16; B hi/lo: [H][N][K] bf16 (K-major)
// C: [H][4096][N] fp32. CTA tile 128x128, 8 warps (2x4), warp tile 64x32.
// K-chunk 32; 2-stage cp.async pipeline; term-major MMA bursts (16 apart).
#define KC 32
#define PB 40                         // smem row pitch in bf16 (80 B)
#define REG_BYTES (128 * PB * 2)      // one operand tile: 10240 B
#define STAGE_BYTES (4 * REG_BYTES)   // Ah/Al/Bh/Bl: 40960 B
#define GEMM_SMEM (2 * STAGE_BYTES)   // 81920 B

__global__ void __launch_bounds__(256, 2) mma_gemm_k(
    const __nv_bfloat16* __restrict__ Ah, const __nv_bfloat16* __restrict__ Al,
    const __nv_bfloat16* __restrict__ Bh, const __nv_bfloat16* __restrict__ Bl,
    float* __restrict__ C, int K, int N)
{
    extern __shared__ __align__(16) char dsm[];
    const uint32_t base = smem_to_u32(dsm);

    const int tid = threadIdx.x, lane = tid & 31, wid = tid >> 5;
    const int m0 = blockIdx.y * 128, n0 = blockIdx.x * 128, h = blockIdx.z;
    const int wm = (wid & 1) * 64;        // warp m offset
    const int wn = (wid >> 1) * 32;       // warp n offset

    // ---- global->smem chunk mapping: 512 16B-chunks per tile, 2 per thread
    const int r0 = tid >> 2, s0 = (tid & 3);
    const int r1 = (tid + 256) >> 2, s1 = ((tid + 256) & 3);
    const uint32_t d0 = (uint32_t)r0 * 80u + (uint32_t)s0 * 16u;
    const uint32_t d1 = (uint32_t)r1 * 80u + (uint32_t)s1 * 16u;
    const __nv_bfloat16* pA0h = Ah + (long)(m0 + r0) * K + s0 * 8;
    const __nv_bfloat16* pA1h = Ah + (long)(m0 + r1) * K + s1 * 8;
    const __nv_bfloat16* pA0l = Al + (long)(m0 + r0) * K + s0 * 8;
    const __nv_bfloat16* pA1l = Al + (long)(m0 + r1) * K + s1 * 8;
    const __nv_bfloat16* pB0h = Bh + ((long)h * N + n0 + r0) * K + s0 * 8;
    const __nv_bfloat16* pB1h = Bh + ((long)h * N + n0 + r1) * K + s1 * 8;
    const __nv_bfloat16* pB0l = Bl + ((long)h * N + n0 + r0) * K + s0 * 8;
    const __nv_bfloat16* pB1l = Bl + ((long)h * N + n0 + r1) * K + s1 * 8;

    // ---- ldmatrix lane address offsets (bytes, within one operand tile)
    const uint32_t aoff = (uint32_t)(wm + (lane & 15)) * 80u + (uint32_t)(lane >> 4) * 16u;
    const uint32_t boff = (uint32_t)(wn + (lane & 7) + ((lane >> 4) << 3)) * 80u
                        + (uint32_t)((lane >> 3) & 1) * 16u;

    float acc[4][4][4];
#pragma unroll
    for (int i = 0; i < 4; i++)
#pragma unroll
        for (int j = 0; j < 4; j++)
#pragma unroll
            for (int q = 0; q < 4; q++) acc[i][j][q] = 0.f;

    const int nk = K / KC;

#define ISSUE_STAGE(T) do {                                              \
        const uint32_t sb = base + ((T) & 1) * STAGE_BYTES;              \
        const long ko = (long)(T) * KC;                                  \
        CPASYNC16(sb + d0, pA0h + ko);                                   \
        CPASYNC16(sb + d1, pA1h + ko);                                   \
        CPASYNC16(sb + REG_BYTES + d0, pA0l + ko);                       \
        CPASYNC16(sb + REG_BYTES + d1, pA1l + ko);                       \
        CPASYNC16(sb + 2 * REG_BYTES + d0, pB0h + ko);                   \
        CPASYNC16(sb + 2 * REG_BYTES + d1, pB1h + ko);                   \
        CPASYNC16(sb + 3 * REG_BYTES + d0, pB0l + ko);                   \
        CPASYNC16(sb + 3 * REG_BYTES + d1, pB1l + ko);                   \
        asm volatile("cp.async.commit_group;" ::: "memory");             \
    } while (0)

    ISSUE_STAGE(0);

    for (int t = 0; t < nk; t++) {
        if (t + 1 < nk) {
            ISSUE_STAGE(t + 1);
            asm volatile("cp.async.wait_group 1;" ::: "memory");
        } else {
            asm volatile("cp.async.wait_group 0;" ::: "memory");
        }
        __syncthreads();

        const uint32_t sb  = base + (t & 1) * STAGE_BYTES;
        const uint32_t uAh = sb;
        const uint32_t uAl = sb + REG_BYTES;
        const uint32_t uBh = sb + 2 * REG_BYTES;
        const uint32_t uBl = sb + 3 * REG_BYTES;

#pragma unroll
        for (int kk = 0; kk < 2; kk++) {
            const uint32_t kb = kk * 32;    // 16 bf16 = 32 bytes
            uint32_t af[4][4], bh[2][4], bl[2][4];
            // load A-hi and B-hi fragments
#pragma unroll
            for (int ma = 0; ma < 4; ma++)
                LDSM4(af[ma][0], af[ma][1], af[ma][2], af[ma][3],
                      uAh + aoff + ma * 1280u + kb);
#pragma unroll
            for (int g = 0; g < 2; g++)
                LDSM4(bh[g][0], bh[g][1], bh[g][2], bh[g][3],
                      uBh + boff + g * 1280u + kb);
            // term 1: Ah*Bh (16 independent accumulators -> no RAW stalls)
#pragma unroll
            for (int ma = 0; ma < 4; ma++)
#pragma unroll
                for (int na = 0; na < 4; na++) {
                    const int g = na >> 1, p = (na & 1) * 2;
                    MMA16816(acc[ma][na], af[ma], bh[g][p], bh[g][p + 1]);
                }
            // load B-lo (overlaps with term-1 MMA drain)
#pragma unroll
            for (int g = 0; g < 2; g++)
                LDSM4(bl[g][0], bl[g][1], bl[g][2], bl[g][3],
                      uBl + boff + g * 1280u + kb);
            // term 2: Ah*Bl (dependent MMA on same acc is 16 issues away)
#pragma unroll
            for (int ma = 0; ma < 4; ma++)
#pragma unroll
                for (int na = 0; na < 4; na++) {
                    const int g = na >> 1, p = (na & 1) * 2;
                    MMA16816(acc[ma][na], af[ma], bl[g][p], bl[g][p + 1]);
                }
            // reload A-lo over af, term 3: Al*Bh
#pragma unroll
            for (int ma = 0; ma < 4; ma++)
                LDSM4(af[ma][0], af[ma][1], af[ma][2], af[ma][3],
                      uAl + aoff + ma * 1280u + kb);
#pragma unroll
            for (int ma = 0; ma < 4; ma++)
#pragma unroll
                for (int na = 0; na < 4; na++) {
                    const int g = na >> 1, p = (na & 1) * 2;
                    MMA16816(acc[ma][na], af[ma], bh[g][p], bh[g][p + 1]);
                }
        }
        __syncthreads();
    }
#undef ISSUE_STAGE

    // ---- epilogue: acc layout m16n8 -> C
    float* Ch = C + (long)h * NNODE * N;
#pragma unroll
    for (int ma = 0; ma < 4; ma++) {
        const int row = m0 + wm + ma * 16 + (lane >> 2);
#pragma unroll
        for (int na = 0; na < 4; na++) {
            const int col = n0 + wn + na * 8 + (lane & 3) * 2;
            float* p = Ch + (long)row * N + col;
            *(float2*)p             = make_float2(acc[ma][na][0], acc[ma][na][1]);
            *(float2*)(p + 8L * N)  = make_float2(acc[ma][na][2], acc[ma][na][3]);
        }
    }
}

// --------------------------- f1/f2 projections ----------------------------
__global__ __launch_bounds__(256) void f12_k(
    const float* __restrict__ Wh, const float* __restrict__ a, int D)
{
    int lane = threadIdx.x & 31;
    int n = (blockIdx.x * blockDim.x + threadIdx.x) >> 5;
    int h = blockIdx.y;
    if (n >= NNODE) return;
    const float* w  = Wh + ((long)h * NNODE + n) * D;
    const float* ah = a + h * 2 * D;
    float s1 = 0.f, s2 = 0.f;
    for (int d = lane; d < D; d += 32) {
        float v = w[d];
        s1 = fmaf(v, ah[d], s1);
        s2 = fmaf(v, ah[D + d], s2);
    }
    for (int off = 16; off; off >>= 1) {
        s1 += __shfl_down_sync(0xffffffffu, s1, off);
        s2 += __shfl_down_sync(0xffffffffu, s2, off);
    }
    if (lane == 0) { g_f1[h * NNODE + n] = s1; g_f2[h * NNODE + n] = s2; }
}

// column mean of Wh per head (deg==0 fallback) — two-stage reduction
__global__ __launch_bounds__(256) void colmean1_k(const float* __restrict__ Wh, int D)
{
    int chunk = blockIdx.x, h = blockIdx.y;
    const int per = NNODE / CMCH;
    const float* base = Wh + (long)h * NNODE * D + (long)chunk * per * D;
    for (int d = threadIdx.x; d < D; d += 256) {
        float s = 0.f;
        for (int n = 0; n < per; n++) s += base[(long)n * D + d];
        g_cmp[((long)h * CMCH + chunk) * D + d] = s;
    }
}
__global__ __launch_bounds__(256) void colmean2_k(int D)
{
    int d = blockIdx.x * blockDim.x + threadIdx.x;
    int h = blockIdx.y;
    if (d >= D) return;
    float s = 0.f;
    const float* p = g_cmp + (long)h * CMCH * D + d;
    for (int c = 0; c < CMCH; c++) s += p[(long)c * D];
    g_cm[h * D + d] = s * (1.f / NNODE);
}

// ------------------- sparse softmax + aggregate (concat) -------------------
// Writes the next layer's A operand directly as bf16 hi/lo.
__global__ __launch_bounds__(256) void agg_concat_k(
    const float* __restrict__ Wh, int H)
{
    const int D = 256;
    int i = blockIdx.x, h = blockIdx.y, t = threadIdx.x;
    __shared__ float sw[MAXN];
    __shared__ int   snb[MAXN];
    __shared__ float red[256];
    int dg = g_deg[i];
    const int* nb = g_nbr + (long)i * MAXN;
    float f1i = g_f1[h * NNODE + i];
    float lmax = -3.4e38f;
    for (int jj = t; jj < dg; jj += 256) {
        int j = nb[jj];
        snb[jj] = j;
        float e = f1i + g_f2[h * NNODE + j];
        e = e >= 0.f ? e : 0.2f * e;          // leaky_relu(alpha=0.2)
        sw[jj] = e;
        lmax = fmaxf(lmax, e);
    }
    red[t] = lmax; __syncthreads();
    for (int s = 128; s > 0; s >>= 1) { if (t < s) red[t] = fmaxf(red[t], red[t + s]); __syncthreads(); }
    float m = red[0]; __syncthreads();
    float lsum = 0.f;
    for (int jj = t; jj < dg; jj += 256) { float w = expf(sw[jj] - m); sw[jj] = w; lsum += w; }
    red[t] = lsum; __syncthreads();
    for (int s = 128; s > 0; s >>= 1) { if (t < s) red[t] += red[t + s]; __syncthreads(); }
    float inv = 1.f / red[0]; __syncthreads();

    float acc;
    if (dg > 0) {
        const float* whh = Wh + (long)h * NNODE * D;
        float a0 = 0.f, a1 = 0.f, a2 = 0.f, a3 = 0.f;
        int jj = 0;
        for (; jj + 4 <= dg; jj += 4) {
            a0 = fmaf(sw[jj + 0], (whh + (long)snb[jj + 0] * D)[t], a0);
            a1 = fmaf(sw[jj + 1], (whh + (long)snb[jj + 1] * D)[t], a1);
            a2 = fmaf(sw[jj + 2], (whh + (long)snb[jj + 2] * D)[t], a2);
            a3 = fmaf(sw[jj + 3], (whh + (long)snb[jj + 3] * D)[t], a3);
        }
        for (; jj < dg; jj++) a0 = fmaf(sw[jj], (whh + (long)snb[jj] * D)[t], a0);
        acc = ((a0 + a1) + (a2 + a3)) * inv;
    } else {
        acc = g_cm[h * D + t];                // uniform softmax over all nodes
    }
    acc = eluf(eluf(acc));                    // reference applies elu twice
    __nv_bfloat16 hv = __float2bfloat16(acc);
    long o = (long)i * (H * D) + h * D + t;
    g_Ah[o] = hv;
    g_Al[o] = __float2bfloat16(acc - __bfloat162float(hv));
}

// ------------- output layer: 6 heads, mean, elu, L2-normalize -------------
__global__ __launch_bounds__(256) void agg_mean_norm_k(
    const float* __restrict__ Wh, float* __restrict__ out)
{
    const int D = 512;
    int i = blockIdx.x, t = threadIdx.x;
    __shared__ float sw[MAXN];
    __shared__ int   snb[MAXN];
    __shared__ float red[256];
    int dg = g_deg[i];
    const int* nb = g_nbr + (long)i * MAXN;
    for (int jj = t; jj < dg; jj += 256) snb[jj] = nb[jj];
    __syncthreads();

    float acc0 = 0.f, acc1 = 0.f;
    for (int h = 0; h < 6; h++) {
        float f1i = g_f1[h * NNODE + i];
        float lmax = -3.4e38f;
        for (int jj = t; jj < dg; jj += 256) {
            float e = f1i + g_f2[h * NNODE + snb[jj]];
            e = e >= 0.f ? e : 0.2f * e;
            sw[jj] = e;
            lmax = fmaxf(lmax, e);
        }
        red[t] = lmax; __syncthreads();
        for (int s = 128; s > 0; s >>= 1) { if (t < s) red[t] = fmaxf(red[t], red[t + s]); __syncthreads(); }
        float m = red[0]; __syncthreads();
        float lsum = 0.f;
        for (int jj = t; jj < dg; jj += 256) { float w = expf(sw[jj] - m); sw[jj] = w; lsum += w; }
        red[t] = lsum; __syncthreads();
        for (int s = 128; s > 0; s >>= 1) { if (t < s) red[t] += red[t + s]; __syncthreads(); }
        float inv = 1.f / red[0]; __syncthreads();

        if (dg > 0) {
            const float* whh = Wh + (long)h * NNODE * D;
            float a0 = 0.f, a1 = 0.f, b0 = 0.f, b1 = 0.f;
            int jj = 0;
            for (; jj + 2 <= dg; jj += 2) {
                const float* ra = whh + (long)snb[jj] * D;
                const float* rb = whh + (long)snb[jj + 1] * D;
                float wa = sw[jj], wb = sw[jj + 1];
                a0 = fmaf(wa, ra[t], a0);
                a1 = fmaf(wa, ra[t + 256], a1);
                b0 = fmaf(wb, rb[t], b0);
                b1 = fmaf(wb, rb[t + 256], b1);
            }
            if (jj < dg) {
                const float* ra = whh + (long)snb[jj] * D;
                float wa = sw[jj];
                a0 = fmaf(wa, ra[t], a0);
                a1 = fmaf(wa, ra[t + 256], a1);
            }
            acc0 += (a0 + b0) * inv;
            acc1 += (a1 + b1) * inv;
        } else {
            acc0 += g_cm[h * D + t];
            acc1 += g_cm[h * D + t + 256];
        }
        __syncthreads();   // sw reused next head
    }
    acc0 *= (1.f / 6.f); acc1 *= (1.f / 6.f);
    acc0 = eluf(acc0);   acc1 = eluf(acc1);
    red[t] = acc0 * acc0 + acc1 * acc1; __syncthreads();
    for (int s = 128; s > 0; s >>= 1) { if (t < s) red[t] += red[t + s]; __syncthreads(); }
    float nrm = sqrtf(red[0]);
    float inv2 = 1.f / fmaxf(nrm, 1e-12f);
    out[(long)i * D + t]       = acc0 * inv2;
    out[(long)i * D + t + 256] = acc1 * inv2;
}

// ------------------------------- launcher ----------------------------------
extern "C" void kernel_launch(void* const* d_in, const int* in_sizes, int n_in,
                              void* d_out, int out_size) {
    const float* x   = (const float*)d_in[0];   // [4096, 2048]
    const float* adj = (const float*)d_in[1];   // [4096, 4096]
    const float* W1  = (const float*)d_in[2];   // [4, 2048, 256]
    const float* a1  = (const float*)d_in[3];   // [4, 512]
    const float* W2  = (const float*)d_in[4];   // [4, 1024, 256]
    const float* a2  = (const float*)d_in[5];   // [4, 512]
    const float* W3  = (const float*)d_in[6];   // [6, 1024, 512]
    const float* a3  = (const float*)d_in[7];   // [6, 1024]
    float* out = (float*)d_out;                 // [4096, 512]

    static int attr_set = 0;
    if (!attr_set) {
        cudaFuncSetAttribute(mma_gemm_k,
                             cudaFuncAttributeMaxDynamicSharedMemorySize, GEMM_SMEM);
        attr_set = 1;
    }

    float* pWh = nullptr;
    __nv_bfloat16 *pAh = nullptr, *pAl = nullptr, *pBh = nullptr, *pBl = nullptr;
    cudaGetSymbolAddress((void**)&pWh, g_Wh);
    cudaGetSymbolAddress((void**)&pAh, g_Ah);
    cudaGetSymbolAddress((void**)&pAl, g_Al);
    cudaGetSymbolAddress((void**)&pBh, g_Bh);
    cudaGetSymbolAddress((void**)&pBl, g_Bl);

    build_nbr_k<<<512, 256>>>(adj);

    // ---- layer 1: H=4, K=2048, N(out)=256 ----
    split_x_k<<<4096, 256>>>(x, 4096L * 2048);
    wsplit_k<<<dim3(64, 8, 4), 256>>>(W1, 2048, 256);
    mma_gemm_k<<<dim3(2, 32, 4), 256, GEMM_SMEM>>>(pAh, pAl, pBh, pBl, pWh, 2048, 256);
    f12_k<<<dim3(512, 4), 256>>>(pWh, a1, 256);
    colmean1_k<<<dim3(CMCH, 4), 256>>>(pWh, 256);
    colmean2_k<<<dim3(1, 4), 256>>>(256);
    agg_concat_k<<<dim3(NNODE, 4), 256>>>(pWh, 4);   // writes g_Ah/g_Al [4096,1024]

    // ---- layer 2: H=4, K=1024, N(out)=256 ----
    wsplit_k<<<dim3(32, 8, 4), 256>>>(W2, 1024, 256);
    mma_gemm_k<<<dim3(2, 32, 4), 256, GEMM_SMEM>>>(pAh, pAl, pBh, pBl, pWh, 1024, 256);
    f12_k<<<dim3(512, 4), 256>>>(pWh, a2, 256);
    colmean1_k<<<dim3(CMCH, 4), 256>>>(pWh, 256);
    colmean2_k<<<dim3(1, 4), 256>>>(256);
    agg_concat_k<<<dim3(NNODE, 4), 256>>>(pWh, 4);   // writes g_Ah/g_Al [4096,1024]

    // ---- output layer: H=6, K=1024, N(out)=512, mean+elu+normalize ----
    wsplit_k<<<dim3(32, 16, 6), 256>>>(W3, 1024, 512);
    mma_gemm_k<<<dim3(4, 32, 6), 256, GEMM_SMEM>>>(pAh, pAl, pBh, pBl, pWh, 1024, 512);
    f12_k<<<dim3(512, 6), 256>>>(pWh, a3, 512);
    colmean1_k<<<dim3(CMCH, 6), 256>>>(pWh, 512);
    colmean2_k<<<dim3(2, 6), 256>>>(512);
    agg_mean_norm_k<<<NNODE, 256>>>(pWh, out);
}